// round 12
// baseline (speedup 1.0000x reference)
#include <cuda_runtime.h>
#include <math.h>

#define BATCH 4
#define NPTS  8192
#define KNB   16
#define NPOS  (BATCH*NPTS*KNB)   // 524288
#define NQ    (BATCH*NPTS)       // 32768
#define CAP   48
#define NPART 4

__device__ int g_idx[NQ*KNB];
__device__ unsigned long long g_sbuf[(long long)NQ*NPART*CAP];
__device__ int g_scnt[NQ*NPART];
__device__ float g_out1[(long long)NPOS*64];   // 134 MB
__device__ float g_x1[(long long)NQ*64];       // 8 MB

typedef unsigned long long u64;

__device__ __forceinline__ u64 pk2(float x, float y) {
    u64 r; asm("mov.b64 %0,{%1,%2};" : "=l"(r) : "f"(x), "f"(y)); return r;
}
__device__ __forceinline__ float2 up2(u64 v) {
    float2 r; asm("mov.b64 {%0,%1},%2;" : "=f"(r.x), "=f"(r.y) : "l"(v)); return r;
}
__device__ __forceinline__ void fma2(u64& d, u64 a, u64 b) {
    asm("fma.rn.f32x2 %0,%1,%2,%0;" : "+l"(d) : "l"(a), "l"(b));
}
__device__ __forceinline__ float leaky(float v) { return v >= 0.f ? v : 0.2f*v; }

// =====================================================================
// KNN (unchanged)
// =====================================================================
__device__ __forceinline__ void bitonic32(float s[32]) {
#pragma unroll
    for (int k = 2; k <= 32; k <<= 1) {
#pragma unroll
        for (int j = k >> 1; j > 0; j >>= 1) {
#pragma unroll
            for (int ii = 0; ii < 32; ii++) {
                int l = ii ^ j;
                if (l > ii) {
                    float lo = fminf(s[ii], s[l]);
                    float hi = fmaxf(s[ii], s[l]);
                    bool up = ((ii & k) == 0);
                    s[ii] = up ? lo : hi;
                    s[l]  = up ? hi : lo;
                }
            }
        }
    }
}

__device__ __forceinline__ void exact16(const float4* tile, float x2, float y2,
                                        float z2, int c0, u64 buf[16]) {
    float bd[16]; int bj[16];
#pragma unroll
    for (int t = 0; t < 16; t++) { bd[t] = 3.4e38f; bj[t] = 0; }
    float cm = 3.4e38f;
    for (int j = 0; j < 2048; j++) {
        float4 p = tile[j];
        float d = fmaf(x2, p.x, fmaf(y2, p.y, fmaf(z2, p.z, p.w)));
        if (d < cm) {
            int am = 0; float mv = bd[0];
#pragma unroll
            for (int u = 1; u < 16; u++) if (bd[u] > mv) { mv = bd[u]; am = u; }
#pragma unroll
            for (int u = 0; u < 16; u++) if (u == am) { bd[u] = d; bj[u] = c0 + j; }
            cm = bd[0];
#pragma unroll
            for (int u = 1; u < 16; u++) cm = fmaxf(cm, bd[u]);
        }
    }
#pragma unroll
    for (int t = 0; t < 16; t++) buf[t] = pk2(bd[t], __int_as_float(bj[t]));
}

__global__ __launch_bounds__(128) void knn_part(const float* __restrict__ xyz)
{
    extern __shared__ float4 tile[];
    const int tid = threadIdx.x;
    const int quarter = blockIdx.x & 3;
    const int qb = (blockIdx.x >> 2) & 31;
    const int b  = blockIdx.x >> 7;
    const int i0 = qb*256 + tid;
    const int i1 = i0 + 128;
    const float* xb = xyz + b*3*NPTS;
    const int c0 = quarter*2048;

    for (int l = tid; l < 512; l += 128) {
        float4 vx = ((const float4*)(xb + c0))[l];
        float4 vy = ((const float4*)(xb + NPTS + c0))[l];
        float4 vz = ((const float4*)(xb + 2*NPTS + c0))[l];
        tile[4*l+0] = make_float4(vx.x, vy.x, vz.x, fmaf(vx.x,vx.x, fmaf(vy.x,vy.x, vz.x*vz.x)));
        tile[4*l+1] = make_float4(vx.y, vy.y, vz.y, fmaf(vx.y,vx.y, fmaf(vy.y,vy.y, vz.y*vz.y)));
        tile[4*l+2] = make_float4(vx.z, vy.z, vz.z, fmaf(vx.z,vx.z, fmaf(vy.z,vy.z, vz.z*vz.z)));
        tile[4*l+3] = make_float4(vx.w, vy.w, vz.w, fmaf(vx.w,vx.w, fmaf(vy.w,vy.w, vz.w*vz.w)));
    }
    __syncthreads();

    const float x20 = -2.0f*xb[i0], y20 = -2.0f*xb[NPTS+i0], z20 = -2.0f*xb[2*NPTS+i0];
    const float x21 = -2.0f*xb[i1], y21 = -2.0f*xb[NPTS+i1], z21 = -2.0f*xb[2*NPTS+i1];

    float s0[32], s1[32];
#pragma unroll
    for (int t = 0; t < 32; t++) { s0[t] = 3.4e38f; s1[t] = 3.4e38f; }
    for (int j0 = 0; j0 < 2048; j0 += 32) {
#pragma unroll
        for (int u = 0; u < 32; u++) {
            float4 p = tile[j0+u];
            float d0 = fmaf(x20, p.x, fmaf(y20, p.y, fmaf(z20, p.z, p.w)));
            float d1 = fmaf(x21, p.x, fmaf(y21, p.y, fmaf(z21, p.z, p.w)));
            s0[u] = fminf(s0[u], d0);
            s1[u] = fminf(s1[u], d1);
        }
    }

    bitonic32(s0);
    bitonic32(s1);
    const float T0 = s0[15], T1 = s1[15];

    u64 buf0[CAP], buf1[CAP];
    int cnt0 = 0, cnt1 = 0, ovf0 = 0, ovf1 = 0;
    for (int j = 0; j < 2048; j++) {
        float4 p = tile[j];
        float d0 = fmaf(x20, p.x, fmaf(y20, p.y, fmaf(z20, p.z, p.w)));
        float d1 = fmaf(x21, p.x, fmaf(y21, p.y, fmaf(z21, p.z, p.w)));
        if (d0 <= T0) {
            if (cnt0 < CAP) { buf0[cnt0] = pk2(d0, __int_as_float(c0+j)); cnt0++; }
            else ovf0 = 1;
        }
        if (d1 <= T1) {
            if (cnt1 < CAP) { buf1[cnt1] = pk2(d1, __int_as_float(c0+j)); cnt1++; }
            else ovf1 = 1;
        }
    }

    if (ovf0) { exact16(tile, x20, y20, z20, c0, buf0); cnt0 = 16; }
    if (ovf1) { exact16(tile, x21, y21, z21, c0, buf1); cnt1 = 16; }

    {
        const int qg = b*NPTS + i0;
        g_scnt[qg*NPART + quarter] = cnt0;
        u64* dst = g_sbuf + (long long)(qg*NPART + quarter)*CAP;
        for (int t = 0; t < cnt0; t++) dst[t] = buf0[t];
    }
    {
        const int qg = b*NPTS + i1;
        g_scnt[qg*NPART + quarter] = cnt1;
        u64* dst = g_sbuf + (long long)(qg*NPART + quarter)*CAP;
        for (int t = 0; t < cnt1; t++) dst[t] = buf1[t];
    }
}

__global__ __launch_bounds__(256) void knn_merge()
{
    const int q = blockIdx.x*256 + threadIdx.x;
    float bd[16]; int bj[16];
#pragma unroll
    for (int t = 0; t < 16; t++) { bd[t] = 3.4e38f; bj[t] = 0; }
    float cm = 3.4e38f;
#pragma unroll
    for (int h = 0; h < NPART; h++) {
        const int c = g_scnt[q*NPART + h];
        const u64* src = g_sbuf + (long long)(q*NPART + h)*CAP;
        for (int e = 0; e < c; e++) {
            float2 v = up2(src[e]);
            float d = v.x;
            if (d < cm) {
                int am = 0; float mv = bd[0];
#pragma unroll
                for (int u = 1; u < 16; u++) if (bd[u] > mv) { mv = bd[u]; am = u; }
#pragma unroll
                for (int u = 0; u < 16; u++) if (u == am) { bd[u] = d; bj[u] = __float_as_int(v.y); }
                cm = bd[0];
#pragma unroll
                for (int u = 1; u < 16; u++) cm = fmaxf(cm, bd[u]);
            }
        }
    }
#pragma unroll
    for (int t = 0; t < 16; t++) g_idx[q*16 + t] = bj[t];
}

// =====================================================================
// Stage 1 (unchanged from R11): 64-pos tiles, 128 thr, 4 CTAs/SM
// =====================================================================
#define S1A 0
#define S1B 4096
#define S1C 8192
#define S1W 12288
#define S1_FLOATS 13312

template<int KFULL>
__device__ __forceinline__ void ldgA16(float4 r[2], const float* __restrict__ src,
                                       int koff, int tid)
{
#pragma unroll
    for (int it = 0; it < 2; it++) {
        int l = it*128 + tid;
        int o = l & 63, k4 = l >> 6;
        r[it] = *(const float4*)(src + o*KFULL + koff + 4*k4);
    }
}
__device__ __forceinline__ void stsA16(float* __restrict__ dst, const float4 r[2], int tid)
{
#pragma unroll
    for (int it = 0; it < 2; it++) {
        int l = it*128 + tid;
        int o = l & 63, k = (l >> 6)*4;
        dst[(k  )*64+o] = r[it].x; dst[(k+1)*64+o] = r[it].y;
        dst[(k+2)*64+o] = r[it].z; dst[(k+3)*64+o] = r[it].w;
    }
}

__device__ __forceinline__ void gemm8c(const float* __restrict__ w,
                                       const float* __restrict__ a,
                                       int og, int pg, u64 acc[4][4])
{
#pragma unroll
    for (int k = 0; k < 16; k++) {
        const float* wr = w + k*64 + og*8;
        ulonglong2 w01 = *(const ulonglong2*)wr;
        ulonglong2 w23 = *(const ulonglong2*)(wr+4);
        u64 wp[4] = {w01.x,w01.y,w23.x,w23.y};
        float4 av = *(const float4*)(a + k*64 + pg*4);
        u64 as[4] = {pk2(av.x,av.x), pk2(av.y,av.y), pk2(av.z,av.z), pk2(av.w,av.w)};
#pragma unroll
        for (int op = 0; op < 4; op++)
#pragma unroll
            for (int p = 0; p < 4; p++) fma2(acc[op][p], wp[op], as[p]);
    }
}

__global__ void __launch_bounds__(128,4) stage1_kernel(
    const float* __restrict__ xyz,
    const float* __restrict__ w1sc, const float* __restrict__ b1sc,
    const float* __restrict__ w1a,  const float* __restrict__ b1a,
    const float* __restrict__ w1b,  const float* __restrict__ b1b,
    const float* __restrict__ w1c,  const float* __restrict__ b1c)
{
    extern __shared__ float sm[];
    const int tid = threadIdx.x;
    const int pg = tid & 15, og = tid >> 4;
    const int base = blockIdx.x << 6;
    const int b  = base >> 17;
    const int n0 = (base & (NPTS*KNB - 1)) >> 4;
    const int nl = pg >> 2;

    float4 R[2];

    ldgA16<64>(R, w1b, 0, tid);
    for (int l = tid; l < 640; l += 128) {
        int o = l/10, k = l - o*10;
        sm[S1C + 640  + k*64 + o] = w1sc[l];
        sm[S1C + 1280 + k*64 + o] = w1a[l];
    }
    if (tid < 64) {
        int nn = n0 + (tid >> 4);
        const float* xb = xyz + b*3*NPTS;
        int j = g_idx[(b*NPTS + nn)*KNB + (tid & 15)];
        float cx = xb[nn], cy = xb[NPTS+nn], cz = xb[2*NPTS+nn];
        float nx = xb[j],  ny = xb[NPTS+j],  nz = xb[2*NPTS+j];
        float rx = nx-cx, ry = ny-cy, rz = nz-cz;
        float dd = sqrtf(fmaf(rx,rx, fmaf(ry,ry, rz*rz)) + 1e-12f);
        sm[S1C+0*64+tid]=cx; sm[S1C+1*64+tid]=cy; sm[S1C+2*64+tid]=cz;
        sm[S1C+3*64+tid]=nx; sm[S1C+4*64+tid]=ny; sm[S1C+5*64+tid]=nz;
        sm[S1C+6*64+tid]=rx; sm[S1C+7*64+tid]=ry; sm[S1C+8*64+tid]=rz;
        sm[S1C+9*64+tid]=dd;
    }
    __syncthreads();
    stsA16(sm + S1W, R, tid);
    ldgA16<64>(R, w1b, 16, tid);

    {
        u64 accS[4][4], accA[4][4];
#pragma unroll
        for (int op=0;op<4;op++)
#pragma unroll
            for (int p=0;p<4;p++) { accS[op][p]=0ull; accA[op][p]=0ull; }
#pragma unroll
        for (int k = 0; k < 10; k++) {
            const float* wsr = sm + S1C + 640  + k*64 + og*8;
            const float* war = sm + S1C + 1280 + k*64 + og*8;
            ulonglong2 ws01 = *(const ulonglong2*)wsr;
            ulonglong2 ws23 = *(const ulonglong2*)(wsr+4);
            ulonglong2 wa01 = *(const ulonglong2*)war;
            ulonglong2 wa23 = *(const ulonglong2*)(war+4);
            u64 wsp[4] = {ws01.x,ws01.y,ws23.x,ws23.y};
            u64 wap[4] = {wa01.x,wa01.y,wa23.x,wa23.y};
            float4 av = *(const float4*)(sm + S1C + k*64 + pg*4);
            u64 as[4] = {pk2(av.x,av.x), pk2(av.y,av.y), pk2(av.z,av.z), pk2(av.w,av.w)};
#pragma unroll
            for (int op=0;op<4;op++)
#pragma unroll
                for (int p=0;p<4;p++) { fma2(accS[op][p], wsp[op], as[p]); fma2(accA[op][p], wap[op], as[p]); }
        }
#pragma unroll
        for (int op=0;op<4;op++) {
            int o0 = og*8 + 2*op;
            float ba0 = __ldg(b1a + o0), ba1 = __ldg(b1a + o0 + 1);
#pragma unroll
            for (int p=0;p<4;p++) {
                float2 va = up2(accA[op][p]);
                sm[S1A + (o0  )*64 + pg*4 + p] = leaky(va.x + ba0);
                sm[S1A + (o0+1)*64 + pg*4 + p] = leaky(va.y + ba1);
                float2 vs = up2(accS[op][p]);
                sm[S1B + (o0  )*64 + pg*4 + p] = vs.x;
                sm[S1B + (o0+1)*64 + pg*4 + p] = vs.y;
            }
        }
    }
    __syncthreads();

    u64 acc4[4][4];
#define ZERO4 {_Pragma("unroll") for (int op=0;op<4;op++) _Pragma("unroll") for (int p=0;p<4;p++) acc4[op][p]=0ull;}
#define PUMP1(STSF)  { __syncthreads(); STSF(sm + S1W, R, tid); __syncthreads(); }

    ZERO4
#pragma unroll 1
    for (int c = 0; c < 3; c++) {
        if (c > 0) ldgA16<64>(R, w1b, (c+1)*16, tid);
        gemm8c(sm + S1W, sm + S1A + c*1024, og, pg, acc4);
        PUMP1(stsA16)
    }
    ldgA16<64>(R, w1c, 0, tid);
    gemm8c(sm + S1W, sm + S1A + 3*1024, og, pg, acc4);
    PUMP1(stsA16)
#pragma unroll
    for (int op=0;op<4;op++) {
        int o0 = og*8 + 2*op;
        float b0 = __ldg(b1b + o0), b1 = __ldg(b1b + o0 + 1);
#pragma unroll
        for (int p=0;p<4;p++) {
            float2 v = up2(acc4[op][p]);
            sm[S1C + (o0  )*64 + pg*4 + p] = leaky(v.x + b0);
            sm[S1C + (o0+1)*64 + pg*4 + p] = leaky(v.y + b1);
        }
    }
    __syncthreads();

    ZERO4
#pragma unroll 1
    for (int c = 0; c < 3; c++) {
        ldgA16<64>(R, w1c, (c+1)*16, tid);
        gemm8c(sm + S1W, sm + S1C + c*1024, og, pg, acc4);
        PUMP1(stsA16)
    }
    gemm8c(sm + S1W, sm + S1C + 3*1024, og, pg, acc4);
#pragma unroll
    for (int op=0;op<4;op++) {
        int o0 = og*8 + 2*op;
        float bt0 = __ldg(b1c + o0)     + __ldg(b1sc + o0);
        float bt1 = __ldg(b1c + o0 + 1) + __ldg(b1sc + o0 + 1);
        float v0m = -3.4e38f, v1m = -3.4e38f;
#pragma unroll
        for (int p=0;p<4;p++) {
            float2 v = up2(acc4[op][p]);
            float o0v = v.x + sm[S1B + (o0  )*64 + pg*4 + p] + bt0;
            float o1v = v.y + sm[S1B + (o0+1)*64 + pg*4 + p] + bt1;
            sm[S1B + (o0  )*64 + pg*4 + p] = o0v;
            sm[S1B + (o0+1)*64 + pg*4 + p] = o1v;
            v0m = fmaxf(v0m, o0v); v1m = fmaxf(v1m, o1v);
        }
        v0m = fmaxf(v0m, __shfl_xor_sync(0xffffffffu, v0m, 1));
        v0m = fmaxf(v0m, __shfl_xor_sync(0xffffffffu, v0m, 2));
        v1m = fmaxf(v1m, __shfl_xor_sync(0xffffffffu, v1m, 1));
        v1m = fmaxf(v1m, __shfl_xor_sync(0xffffffffu, v1m, 2));
        if ((pg & 3) == 0) {
            long long q = (long long)(b*NPTS + n0 + nl);
            g_x1[q*64 + o0]     = v0m;
            g_x1[q*64 + o0 + 1] = v1m;
        }
    }
    __syncthreads();
    for (int l = tid; l < 1024; l += 128)
        ((float4*)(g_out1 + (long long)blockIdx.x*4096))[l] = ((const float4*)(sm + S1B))[l];
}

// =====================================================================
// Stage 2: 128-pos tiles, 256 thr, 2 CTAs/SM — position-paired accs.
// og = tid>>4 (0..15), pg = tid&15 (8 pos each), nn = pg>>1.
// smem: B1 0, B2 8192, B3 16384, SW 24576(1024), SX 25600(512)
// =====================================================================
#define T2B1 0
#define T2B2 8192
#define T2B3 16384
#define T2SW 24576
#define T2SX 25600
#define T2_FLOATS 26112

template<int KFULL>
__device__ __forceinline__ void ldgA2(float4& r, const float* __restrict__ src,
                                      int koff, int tid)
{
    int o = tid & 63, k4 = tid >> 6;
    r = *(const float4*)(src + o*KFULL + koff + 4*k4);
}
__device__ __forceinline__ void stsA2(float* __restrict__ dst, const float4& r, int tid)
{
    int o = tid & 63, k = (tid >> 6)*4;
    dst[(k  )*64+o] = r.x; dst[(k+1)*64+o] = r.y;
    dst[(k+2)*64+o] = r.z; dst[(k+3)*64+o] = r.w;
}
template<int KFULL>
__device__ __forceinline__ void ldgB2(float4& r, const float* __restrict__ src,
                                      int koff, int tid)
{
    int o = tid & 127, k4 = tid >> 7;
    r = *(const float4*)(src + o*KFULL + koff + 4*k4);
}
__device__ __forceinline__ void stsB2(float* __restrict__ dst, const float4& r, int tid)
{
    int o = tid & 127, k = (tid >> 7)*4;
    dst[(k  )*128+o] = r.x; dst[(k+1)*128+o] = r.y;
    dst[(k+2)*128+o] = r.z; dst[(k+3)*128+o] = r.w;
}

// 4 out x 8 pos (4 pos-pairs), 16-k chunk. w stride 64, act stride 128.
__device__ __forceinline__ void gemm4p(const float* __restrict__ w,
                                       const float* __restrict__ a,
                                       int og, int pg, u64 acc[4][4])
{
#pragma unroll
    for (int k = 0; k < 16; k++) {
        float4 wv = *(const float4*)(w + k*64 + og*4);
        u64 ws[4] = {pk2(wv.x,wv.x), pk2(wv.y,wv.y), pk2(wv.z,wv.z), pk2(wv.w,wv.w)};
        ulonglong2 a01 = *(const ulonglong2*)(a + k*128 + pg*8);
        ulonglong2 a23 = *(const ulonglong2*)(a + k*128 + pg*8 + 4);
        u64 ap[4] = {a01.x, a01.y, a23.x, a23.y};
#pragma unroll
        for (int o = 0; o < 4; o++)
#pragma unroll
            for (int p = 0; p < 4; p++) fma2(acc[o][p], ws[o], ap[p]);
    }
}

// 8 out x 8 pos (4 pos-pairs), 8-k chunk. w stride 128, act stride 128.
__device__ __forceinline__ void gemm8p(const float* __restrict__ w,
                                       const float* __restrict__ a,
                                       int og, int pg, u64 acc[8][4])
{
#pragma unroll
    for (int k = 0; k < 8; k++) {
        const float* wr = w + k*128 + og*8;
        float4 w0 = *(const float4*)wr;
        float4 w1 = *(const float4*)(wr+4);
        u64 ws[8] = {pk2(w0.x,w0.x), pk2(w0.y,w0.y), pk2(w0.z,w0.z), pk2(w0.w,w0.w),
                     pk2(w1.x,w1.x), pk2(w1.y,w1.y), pk2(w1.z,w1.z), pk2(w1.w,w1.w)};
        ulonglong2 a01 = *(const ulonglong2*)(a + k*128 + pg*8);
        ulonglong2 a23 = *(const ulonglong2*)(a + k*128 + pg*8 + 4);
        u64 ap[4] = {a01.x, a01.y, a23.x, a23.y};
#pragma unroll
        for (int o = 0; o < 8; o++)
#pragma unroll
            for (int p = 0; p < 4; p++) fma2(acc[o][p], ws[o], ap[p]);
    }
}

__global__ void __launch_bounds__(256,2) stage2_kernel(
    const float* __restrict__ w2sc, const float* __restrict__ b2sc,
    const float* __restrict__ w2a,  const float* __restrict__ b2a,
    const float* __restrict__ w2b,  const float* __restrict__ b2b,
    const float* __restrict__ w2c,  const float* __restrict__ b2c,
    float* __restrict__ outp)
{
    extern __shared__ float sm[];
    const int tid = threadIdx.x;
    const int og = tid >> 4, pg = tid & 15;      // og 0..15, 8 pos per pg
    const int nn = pg >> 1;                      // thread's n (0..7)
    const int base = blockIdx.x << 7;
    const int b  = base >> 17;
    const int nb = (base & (NPTS*KNB - 1)) >> 4;

    float4 R;

    // ---- prologue: out1 -> B1, x1 -> SX ; prefetch w2a chunk0 ----
    ldgA2<128>(R, w2a, 0, tid);
    {
        const float4* src = (const float4*)(g_out1 + (long long)blockIdx.x*8192);
        for (int l = tid; l < 2048; l += 256) {
            int t = l >> 10, i = l & 1023;
            int ch = i >> 4, p4 = i & 15;
            *(float4*)(sm + T2B1 + ch*128 + t*64 + p4*4) = src[l];
        }
    }
    for (int l = tid; l < 512; l += 256) {
        int ch = l >> 3, q = l & 7;
        sm[T2SX + ch*8 + q] = g_x1[(long long)(b*NPTS + nb + q)*64 + ch];
    }
    __syncthreads();
    stsA2(sm + T2SW, R, tid);
    ldgA2<128>(R, w2a, 16, tid);
    __syncthreads();

    u64 acc4[4][4];
#define ZERO4B {_Pragma("unroll") for (int op=0;op<4;op++) _Pragma("unroll") for (int p=0;p<4;p++) acc4[op][p]=0ull;}
#define PUMP2(STSF)  { __syncthreads(); STSF(sm + T2SW, R, tid); __syncthreads(); }

    // ---- a main (w2a k0..63, 4 chunks) on B1: 4 out x 8 pos ----
    ZERO4B
    gemm4p(sm + T2SW, sm + T2B1, og, pg, acc4);
    PUMP2(stsA2)
    ldgA2<128>(R, w2a, 32, tid);
    gemm4p(sm + T2SW, sm + T2B1 + 16*128, og, pg, acc4);
    PUMP2(stsA2)
    ldgA2<128>(R, w2a, 48, tid);
    gemm4p(sm + T2SW, sm + T2B1 + 32*128, og, pg, acc4);
    PUMP2(stsA2)
    ldgA2<128>(R, w2a, 64, tid);
    gemm4p(sm + T2SW, sm + T2B1 + 48*128, og, pg, acc4);
    PUMP2(stsA2)

    // ---- a x1-corr (w2a k64..127, 4x16 cols): out-paired cr (4 outs) ----
    u64 crA[2] = {0,0};
#define CORRA(C0) \
    _Pragma("unroll") \
    for (int cc = 0; cc < 16; cc++) { \
        ulonglong2 w01 = *(const ulonglong2*)(sm + T2SW + cc*64 + og*4); \
        float xv = sm[T2SX + ((C0)+cc)*8 + nn]; \
        u64 xs = pk2(xv, xv); \
        fma2(crA[0], w01.x, xs); fma2(crA[1], w01.y, xs); \
    }
    ldgA2<128>(R, w2a, 80, tid);
    CORRA(0)
    PUMP2(stsA2)
    ldgA2<128>(R, w2a, 96, tid);
    CORRA(16)
    PUMP2(stsA2)
    ldgA2<128>(R, w2a, 112, tid);
    CORRA(32)
    PUMP2(stsA2)
    ldgB2<64>(R, w2b, 0, tid);
    CORRA(48)
    PUMP2(stsB2)

    // ---- a epilogue: h -> B2 (4 outs, 8 pos) ----
#pragma unroll
    for (int op=0;op<4;op++) {
        int o = og*4 + op;
        float2 cp = up2(crA[op>>1]);
        float cv = (op & 1) ? cp.y : cp.x;
        float bb = __ldg(b2a + o) + cv;
        float* row = sm + T2B2 + o*128 + pg*8;
#pragma unroll
        for (int p=0;p<4;p++) {
            float2 v = up2(acc4[op][p]);
            row[2*p]   = leaky(v.x + bb);
            row[2*p+1] = leaky(v.y + bb);
        }
    }
    __syncthreads();

    // ---- b (w2b, 8 chunks) on B2(h): 8 out x 8 pos ----
    u64 acc[8][4];
#pragma unroll
    for (int op=0;op<8;op++)
#pragma unroll
        for (int p=0;p<4;p++) acc[op][p]=0ull;
#pragma unroll 1
    for (int c = 0; c < 7; c++) {
        ldgB2<64>(R, w2b, (c+1)*8, tid);
        gemm8p(sm + T2SW, sm + T2B2 + c*8*128, og, pg, acc);
        PUMP2(stsB2)
    }
    ldgB2<128>(R, w2c, 0, tid);
    gemm8p(sm + T2SW, sm + T2B2 + 56*128, og, pg, acc);
    PUMP2(stsB2)
    // h2 epilogue: ch<64 -> B3, ch>=64 -> B2
#pragma unroll
    for (int op=0;op<8;op++) {
        int o = og*8 + op;
        float bb = __ldg(b2b + o);
        float* row = sm + ((o < 64) ? (T2B3 + o*128) : (T2B2 + (o-64)*128)) + pg*8;
#pragma unroll
        for (int p=0;p<4;p++) {
            float2 v = up2(acc[op][p]);
            row[2*p]   = leaky(v.x + bb);
            row[2*p+1] = leaky(v.y + bb);
        }
    }
    __syncthreads();

    // ---- c + sc into one accumulator ----
#pragma unroll
    for (int op=0;op<8;op++)
#pragma unroll
        for (int p=0;p<4;p++) acc[op][p]=0ull;
#pragma unroll 1
    for (int c = 0; c < 7; c++) {
        ldgB2<128>(R, w2c, (c+1)*8, tid);
        gemm8p(sm + T2SW, sm + T2B3 + c*8*128, og, pg, acc);
        PUMP2(stsB2)
    }
    ldgB2<128>(R, w2c, 64, tid);
    gemm8p(sm + T2SW, sm + T2B3 + 56*128, og, pg, acc);
    PUMP2(stsB2)
#pragma unroll 1
    for (int c = 0; c < 7; c++) {
        ldgB2<128>(R, w2c, 64 + (c+1)*8, tid);
        gemm8p(sm + T2SW, sm + T2B2 + c*8*128, og, pg, acc);
        PUMP2(stsB2)
    }
    ldgB2<128>(R, w2sc, 0, tid);
    gemm8p(sm + T2SW, sm + T2B2 + 56*128, og, pg, acc);
    PUMP2(stsB2)
#pragma unroll 1
    for (int c = 0; c < 7; c++) {
        ldgB2<128>(R, w2sc, (c+1)*8, tid);
        gemm8p(sm + T2SW, sm + T2B1 + c*8*128, og, pg, acc);
        PUMP2(stsB2)
    }
    ldgB2<128>(R, w2sc, 64, tid);
    gemm8p(sm + T2SW, sm + T2B1 + 56*128, og, pg, acc);
    PUMP2(stsB2)

    // ---- sc x1-corr (8 chunks of 8 cols): out-paired cr2 (8 outs) ----
    u64 cr2[4] = {0,0,0,0};
#define CORRS(C0) \
    _Pragma("unroll") \
    for (int cc = 0; cc < 8; cc++) { \
        const float* wr = sm + T2SW + cc*128 + og*8; \
        ulonglong2 w01 = *(const ulonglong2*)wr; \
        ulonglong2 w23 = *(const ulonglong2*)(wr+4); \
        float xv = sm[T2SX + ((C0)+cc)*8 + nn]; \
        u64 xs = pk2(xv, xv); \
        fma2(cr2[0], w01.x, xs); fma2(cr2[1], w01.y, xs); \
        fma2(cr2[2], w23.x, xs); fma2(cr2[3], w23.y, xs); \
    }
#pragma unroll 1
    for (int c = 0; c < 7; c++) {
        ldgB2<128>(R, w2sc, 64 + (c+1)*8, tid);
        CORRS(c*8)
        PUMP2(stsB2)
    }
    CORRS(56)

    // ---- final epilogue: max over own 8 k, shfl with partner, write ----
#pragma unroll
    for (int op=0;op<8;op++) {
        int o = og*8 + op;
        float2 cp = up2(cr2[op>>1]);
        float cv = (op & 1) ? cp.y : cp.x;
        float bt = __ldg(b2sc + o) + __ldg(b2c + o) + cv;
        float m = -3.4e38f;
#pragma unroll
        for (int p=0;p<4;p++) {
            float2 v = up2(acc[op][p]);
            m = fmaxf(m, fmaxf(v.x, v.y));
        }
        m += bt;
        m = fmaxf(m, __shfl_xor_sync(0xffffffffu, m, 1));
        if ((pg & 1) == 0)
            outp[((long long)b*128 + o)*NPTS + nb + nn] = m;
    }
}

// =====================================================================
extern "C" void kernel_launch(void* const* d_in, const int* in_sizes, int n_in,
                              void* d_out, int out_size)
{
    const float* xyz     = (const float*)d_in[0];
    const float* p1_sc_w = (const float*)d_in[1];
    const float* p1_sc_b = (const float*)d_in[2];
    const float* p1_a_w  = (const float*)d_in[3];
    const float* p1_a_b  = (const float*)d_in[4];
    const float* p1_b_w  = (const float*)d_in[5];
    const float* p1_b_b  = (const float*)d_in[6];
    const float* p1_c_w  = (const float*)d_in[7];
    const float* p1_c_b  = (const float*)d_in[8];
    const float* p2_sc_w = (const float*)d_in[9];
    const float* p2_sc_b = (const float*)d_in[10];
    const float* p2_a_w  = (const float*)d_in[11];
    const float* p2_a_b  = (const float*)d_in[12];
    const float* p2_b_w  = (const float*)d_in[13];
    const float* p2_b_b  = (const float*)d_in[14];
    const float* p2_c_w  = (const float*)d_in[15];
    const float* p2_c_b  = (const float*)d_in[16];
    float* outp = (float*)d_out;

    cudaFuncSetAttribute(stage1_kernel, cudaFuncAttributeMaxDynamicSharedMemorySize,
                         S1_FLOATS*4);
    cudaFuncSetAttribute(stage2_kernel, cudaFuncAttributeMaxDynamicSharedMemorySize,
                         T2_FLOATS*4);

    knn_part<<<512, 128, 32768>>>(xyz);
    knn_merge<<<NQ/256, 256>>>();
    stage1_kernel<<<NPOS/64, 128, S1_FLOATS*4>>>(
        xyz, p1_sc_w, p1_sc_b, p1_a_w, p1_a_b, p1_b_w, p1_b_b, p1_c_w, p1_c_b);
    stage2_kernel<<<NPOS/128, 256, T2_FLOATS*4>>>(
        p2_sc_w, p2_sc_b, p2_a_w, p2_a_b, p2_b_w, p2_b_b, p2_c_w, p2_c_b, outp);
}

// round 13
// speedup vs baseline: 1.1357x; 1.1357x over previous
#include <cuda_runtime.h>
#include <math.h>

#define BATCH 4
#define NPTS  8192
#define KNB   16
#define NPOS  (BATCH*NPTS*KNB)   // 524288
#define NQ    (BATCH*NPTS)       // 32768
#define CAP   48
#define NPART 4

__device__ int g_idx[NQ*KNB];
__device__ unsigned long long g_sbuf[(long long)NQ*NPART*CAP];
__device__ int g_scnt[NQ*NPART];
__device__ float g_out1[(long long)NPOS*64];   // 134 MB
__device__ float g_x1[(long long)NQ*64];       // 8 MB

typedef unsigned long long u64;

__device__ __forceinline__ u64 pk2(float x, float y) {
    u64 r; asm("mov.b64 %0,{%1,%2};" : "=l"(r) : "f"(x), "f"(y)); return r;
}
__device__ __forceinline__ float2 up2(u64 v) {
    float2 r; asm("mov.b64 {%0,%1},%2;" : "=f"(r.x), "=f"(r.y) : "l"(v)); return r;
}
__device__ __forceinline__ void fma2(u64& d, u64 a, u64 b) {
    asm("fma.rn.f32x2 %0,%1,%2,%0;" : "+l"(d) : "l"(a), "l"(b));
}
__device__ __forceinline__ float leaky(float v) { return v >= 0.f ? v : 0.2f*v; }

// =====================================================================
// KNN (unchanged)
// =====================================================================
__device__ __forceinline__ void bitonic32(float s[32]) {
#pragma unroll
    for (int k = 2; k <= 32; k <<= 1) {
#pragma unroll
        for (int j = k >> 1; j > 0; j >>= 1) {
#pragma unroll
            for (int ii = 0; ii < 32; ii++) {
                int l = ii ^ j;
                if (l > ii) {
                    float lo = fminf(s[ii], s[l]);
                    float hi = fmaxf(s[ii], s[l]);
                    bool up = ((ii & k) == 0);
                    s[ii] = up ? lo : hi;
                    s[l]  = up ? hi : lo;
                }
            }
        }
    }
}

__device__ __forceinline__ void exact16(const float4* tile, float x2, float y2,
                                        float z2, int c0, u64 buf[16]) {
    float bd[16]; int bj[16];
#pragma unroll
    for (int t = 0; t < 16; t++) { bd[t] = 3.4e38f; bj[t] = 0; }
    float cm = 3.4e38f;
    for (int j = 0; j < 2048; j++) {
        float4 p = tile[j];
        float d = fmaf(x2, p.x, fmaf(y2, p.y, fmaf(z2, p.z, p.w)));
        if (d < cm) {
            int am = 0; float mv = bd[0];
#pragma unroll
            for (int u = 1; u < 16; u++) if (bd[u] > mv) { mv = bd[u]; am = u; }
#pragma unroll
            for (int u = 0; u < 16; u++) if (u == am) { bd[u] = d; bj[u] = c0 + j; }
            cm = bd[0];
#pragma unroll
            for (int u = 1; u < 16; u++) cm = fmaxf(cm, bd[u]);
        }
    }
#pragma unroll
    for (int t = 0; t < 16; t++) buf[t] = pk2(bd[t], __int_as_float(bj[t]));
}

__global__ __launch_bounds__(128) void knn_part(const float* __restrict__ xyz)
{
    extern __shared__ float4 tile[];
    const int tid = threadIdx.x;
    const int quarter = blockIdx.x & 3;
    const int qb = (blockIdx.x >> 2) & 31;
    const int b  = blockIdx.x >> 7;
    const int i0 = qb*256 + tid;
    const int i1 = i0 + 128;
    const float* xb = xyz + b*3*NPTS;
    const int c0 = quarter*2048;

    for (int l = tid; l < 512; l += 128) {
        float4 vx = ((const float4*)(xb + c0))[l];
        float4 vy = ((const float4*)(xb + NPTS + c0))[l];
        float4 vz = ((const float4*)(xb + 2*NPTS + c0))[l];
        tile[4*l+0] = make_float4(vx.x, vy.x, vz.x, fmaf(vx.x,vx.x, fmaf(vy.x,vy.x, vz.x*vz.x)));
        tile[4*l+1] = make_float4(vx.y, vy.y, vz.y, fmaf(vx.y,vx.y, fmaf(vy.y,vy.y, vz.y*vz.y)));
        tile[4*l+2] = make_float4(vx.z, vy.z, vz.z, fmaf(vx.z,vx.z, fmaf(vy.z,vy.z, vz.z*vz.z)));
        tile[4*l+3] = make_float4(vx.w, vy.w, vz.w, fmaf(vx.w,vx.w, fmaf(vy.w,vy.w, vz.w*vz.w)));
    }
    __syncthreads();

    const float x20 = -2.0f*xb[i0], y20 = -2.0f*xb[NPTS+i0], z20 = -2.0f*xb[2*NPTS+i0];
    const float x21 = -2.0f*xb[i1], y21 = -2.0f*xb[NPTS+i1], z21 = -2.0f*xb[2*NPTS+i1];

    float s0[32], s1[32];
#pragma unroll
    for (int t = 0; t < 32; t++) { s0[t] = 3.4e38f; s1[t] = 3.4e38f; }
    for (int j0 = 0; j0 < 2048; j0 += 32) {
#pragma unroll
        for (int u = 0; u < 32; u++) {
            float4 p = tile[j0+u];
            float d0 = fmaf(x20, p.x, fmaf(y20, p.y, fmaf(z20, p.z, p.w)));
            float d1 = fmaf(x21, p.x, fmaf(y21, p.y, fmaf(z21, p.z, p.w)));
            s0[u] = fminf(s0[u], d0);
            s1[u] = fminf(s1[u], d1);
        }
    }

    bitonic32(s0);
    bitonic32(s1);
    const float T0 = s0[15], T1 = s1[15];

    u64 buf0[CAP], buf1[CAP];
    int cnt0 = 0, cnt1 = 0, ovf0 = 0, ovf1 = 0;
    for (int j = 0; j < 2048; j++) {
        float4 p = tile[j];
        float d0 = fmaf(x20, p.x, fmaf(y20, p.y, fmaf(z20, p.z, p.w)));
        float d1 = fmaf(x21, p.x, fmaf(y21, p.y, fmaf(z21, p.z, p.w)));
        if (d0 <= T0) {
            if (cnt0 < CAP) { buf0[cnt0] = pk2(d0, __int_as_float(c0+j)); cnt0++; }
            else ovf0 = 1;
        }
        if (d1 <= T1) {
            if (cnt1 < CAP) { buf1[cnt1] = pk2(d1, __int_as_float(c0+j)); cnt1++; }
            else ovf1 = 1;
        }
    }

    if (ovf0) { exact16(tile, x20, y20, z20, c0, buf0); cnt0 = 16; }
    if (ovf1) { exact16(tile, x21, y21, z21, c0, buf1); cnt1 = 16; }

    {
        const int qg = b*NPTS + i0;
        g_scnt[qg*NPART + quarter] = cnt0;
        u64* dst = g_sbuf + (long long)(qg*NPART + quarter)*CAP;
        for (int t = 0; t < cnt0; t++) dst[t] = buf0[t];
    }
    {
        const int qg = b*NPTS + i1;
        g_scnt[qg*NPART + quarter] = cnt1;
        u64* dst = g_sbuf + (long long)(qg*NPART + quarter)*CAP;
        for (int t = 0; t < cnt1; t++) dst[t] = buf1[t];
    }
}

__global__ __launch_bounds__(256) void knn_merge()
{
    const int q = blockIdx.x*256 + threadIdx.x;
    float bd[16]; int bj[16];
#pragma unroll
    for (int t = 0; t < 16; t++) { bd[t] = 3.4e38f; bj[t] = 0; }
    float cm = 3.4e38f;
#pragma unroll
    for (int h = 0; h < NPART; h++) {
        const int c = g_scnt[q*NPART + h];
        const u64* src = g_sbuf + (long long)(q*NPART + h)*CAP;
        for (int e = 0; e < c; e++) {
            float2 v = up2(src[e]);
            float d = v.x;
            if (d < cm) {
                int am = 0; float mv = bd[0];
#pragma unroll
                for (int u = 1; u < 16; u++) if (bd[u] > mv) { mv = bd[u]; am = u; }
#pragma unroll
                for (int u = 0; u < 16; u++) if (u == am) { bd[u] = d; bj[u] = __float_as_int(v.y); }
                cm = bd[0];
#pragma unroll
                for (int u = 1; u < 16; u++) cm = fmaxf(cm, bd[u]);
            }
        }
    }
#pragma unroll
    for (int t = 0; t < 16; t++) g_idx[q*16 + t] = bj[t];
}

// =====================================================================
// Stage 1 (unchanged from R11): 64-pos tiles, 128 thr, 4 CTAs/SM
// =====================================================================
#define S1A 0
#define S1B 4096
#define S1C 8192
#define S1W 12288
#define S1_FLOATS 13312

template<int KFULL>
__device__ __forceinline__ void ldgA16(float4 r[2], const float* __restrict__ src,
                                       int koff, int tid)
{
#pragma unroll
    for (int it = 0; it < 2; it++) {
        int l = it*128 + tid;
        int o = l & 63, k4 = l >> 6;
        r[it] = *(const float4*)(src + o*KFULL + koff + 4*k4);
    }
}
__device__ __forceinline__ void stsA16(float* __restrict__ dst, const float4 r[2], int tid)
{
#pragma unroll
    for (int it = 0; it < 2; it++) {
        int l = it*128 + tid;
        int o = l & 63, k = (l >> 6)*4;
        dst[(k  )*64+o] = r[it].x; dst[(k+1)*64+o] = r[it].y;
        dst[(k+2)*64+o] = r[it].z; dst[(k+3)*64+o] = r[it].w;
    }
}

__device__ __forceinline__ void gemm8c(const float* __restrict__ w,
                                       const float* __restrict__ a,
                                       int og, int pg, u64 acc[4][4])
{
#pragma unroll
    for (int k = 0; k < 16; k++) {
        const float* wr = w + k*64 + og*8;
        ulonglong2 w01 = *(const ulonglong2*)wr;
        ulonglong2 w23 = *(const ulonglong2*)(wr+4);
        u64 wp[4] = {w01.x,w01.y,w23.x,w23.y};
        float4 av = *(const float4*)(a + k*64 + pg*4);
        u64 as[4] = {pk2(av.x,av.x), pk2(av.y,av.y), pk2(av.z,av.z), pk2(av.w,av.w)};
#pragma unroll
        for (int op = 0; op < 4; op++)
#pragma unroll
            for (int p = 0; p < 4; p++) fma2(acc[op][p], wp[op], as[p]);
    }
}

__global__ void __launch_bounds__(128,4) stage1_kernel(
    const float* __restrict__ xyz,
    const float* __restrict__ w1sc, const float* __restrict__ b1sc,
    const float* __restrict__ w1a,  const float* __restrict__ b1a,
    const float* __restrict__ w1b,  const float* __restrict__ b1b,
    const float* __restrict__ w1c,  const float* __restrict__ b1c)
{
    extern __shared__ float sm[];
    const int tid = threadIdx.x;
    const int pg = tid & 15, og = tid >> 4;
    const int base = blockIdx.x << 6;
    const int b  = base >> 17;
    const int n0 = (base & (NPTS*KNB - 1)) >> 4;
    const int nl = pg >> 2;

    float4 R[2];

    ldgA16<64>(R, w1b, 0, tid);
    for (int l = tid; l < 640; l += 128) {
        int o = l/10, k = l - o*10;
        sm[S1C + 640  + k*64 + o] = w1sc[l];
        sm[S1C + 1280 + k*64 + o] = w1a[l];
    }
    if (tid < 64) {
        int nn = n0 + (tid >> 4);
        const float* xb = xyz + b*3*NPTS;
        int j = g_idx[(b*NPTS + nn)*KNB + (tid & 15)];
        float cx = xb[nn], cy = xb[NPTS+nn], cz = xb[2*NPTS+nn];
        float nx = xb[j],  ny = xb[NPTS+j],  nz = xb[2*NPTS+j];
        float rx = nx-cx, ry = ny-cy, rz = nz-cz;
        float dd = sqrtf(fmaf(rx,rx, fmaf(ry,ry, rz*rz)) + 1e-12f);
        sm[S1C+0*64+tid]=cx; sm[S1C+1*64+tid]=cy; sm[S1C+2*64+tid]=cz;
        sm[S1C+3*64+tid]=nx; sm[S1C+4*64+tid]=ny; sm[S1C+5*64+tid]=nz;
        sm[S1C+6*64+tid]=rx; sm[S1C+7*64+tid]=ry; sm[S1C+8*64+tid]=rz;
        sm[S1C+9*64+tid]=dd;
    }
    __syncthreads();
    stsA16(sm + S1W, R, tid);
    ldgA16<64>(R, w1b, 16, tid);

    {
        u64 accS[4][4], accA[4][4];
#pragma unroll
        for (int op=0;op<4;op++)
#pragma unroll
            for (int p=0;p<4;p++) { accS[op][p]=0ull; accA[op][p]=0ull; }
#pragma unroll
        for (int k = 0; k < 10; k++) {
            const float* wsr = sm + S1C + 640  + k*64 + og*8;
            const float* war = sm + S1C + 1280 + k*64 + og*8;
            ulonglong2 ws01 = *(const ulonglong2*)wsr;
            ulonglong2 ws23 = *(const ulonglong2*)(wsr+4);
            ulonglong2 wa01 = *(const ulonglong2*)war;
            ulonglong2 wa23 = *(const ulonglong2*)(war+4);
            u64 wsp[4] = {ws01.x,ws01.y,ws23.x,ws23.y};
            u64 wap[4] = {wa01.x,wa01.y,wa23.x,wa23.y};
            float4 av = *(const float4*)(sm + S1C + k*64 + pg*4);
            u64 as[4] = {pk2(av.x,av.x), pk2(av.y,av.y), pk2(av.z,av.z), pk2(av.w,av.w)};
#pragma unroll
            for (int op=0;op<4;op++)
#pragma unroll
                for (int p=0;p<4;p++) { fma2(accS[op][p], wsp[op], as[p]); fma2(accA[op][p], wap[op], as[p]); }
        }
#pragma unroll
        for (int op=0;op<4;op++) {
            int o0 = og*8 + 2*op;
            float ba0 = __ldg(b1a + o0), ba1 = __ldg(b1a + o0 + 1);
#pragma unroll
            for (int p=0;p<4;p++) {
                float2 va = up2(accA[op][p]);
                sm[S1A + (o0  )*64 + pg*4 + p] = leaky(va.x + ba0);
                sm[S1A + (o0+1)*64 + pg*4 + p] = leaky(va.y + ba1);
                float2 vs = up2(accS[op][p]);
                sm[S1B + (o0  )*64 + pg*4 + p] = vs.x;
                sm[S1B + (o0+1)*64 + pg*4 + p] = vs.y;
            }
        }
    }
    __syncthreads();

    u64 acc4[4][4];
#define ZERO4 {_Pragma("unroll") for (int op=0;op<4;op++) _Pragma("unroll") for (int p=0;p<4;p++) acc4[op][p]=0ull;}
#define PUMP1(STSF)  { __syncthreads(); STSF(sm + S1W, R, tid); __syncthreads(); }

    ZERO4
#pragma unroll 1
    for (int c = 0; c < 3; c++) {
        if (c > 0) ldgA16<64>(R, w1b, (c+1)*16, tid);
        gemm8c(sm + S1W, sm + S1A + c*1024, og, pg, acc4);
        PUMP1(stsA16)
    }
    ldgA16<64>(R, w1c, 0, tid);
    gemm8c(sm + S1W, sm + S1A + 3*1024, og, pg, acc4);
    PUMP1(stsA16)
#pragma unroll
    for (int op=0;op<4;op++) {
        int o0 = og*8 + 2*op;
        float b0 = __ldg(b1b + o0), b1 = __ldg(b1b + o0 + 1);
#pragma unroll
        for (int p=0;p<4;p++) {
            float2 v = up2(acc4[op][p]);
            sm[S1C + (o0  )*64 + pg*4 + p] = leaky(v.x + b0);
            sm[S1C + (o0+1)*64 + pg*4 + p] = leaky(v.y + b1);
        }
    }
    __syncthreads();

    ZERO4
#pragma unroll 1
    for (int c = 0; c < 3; c++) {
        ldgA16<64>(R, w1c, (c+1)*16, tid);
        gemm8c(sm + S1W, sm + S1C + c*1024, og, pg, acc4);
        PUMP1(stsA16)
    }
    gemm8c(sm + S1W, sm + S1C + 3*1024, og, pg, acc4);
#pragma unroll
    for (int op=0;op<4;op++) {
        int o0 = og*8 + 2*op;
        float bt0 = __ldg(b1c + o0)     + __ldg(b1sc + o0);
        float bt1 = __ldg(b1c + o0 + 1) + __ldg(b1sc + o0 + 1);
        float v0m = -3.4e38f, v1m = -3.4e38f;
#pragma unroll
        for (int p=0;p<4;p++) {
            float2 v = up2(acc4[op][p]);
            float o0v = v.x + sm[S1B + (o0  )*64 + pg*4 + p] + bt0;
            float o1v = v.y + sm[S1B + (o0+1)*64 + pg*4 + p] + bt1;
            sm[S1B + (o0  )*64 + pg*4 + p] = o0v;
            sm[S1B + (o0+1)*64 + pg*4 + p] = o1v;
            v0m = fmaxf(v0m, o0v); v1m = fmaxf(v1m, o1v);
        }
        v0m = fmaxf(v0m, __shfl_xor_sync(0xffffffffu, v0m, 1));
        v0m = fmaxf(v0m, __shfl_xor_sync(0xffffffffu, v0m, 2));
        v1m = fmaxf(v1m, __shfl_xor_sync(0xffffffffu, v1m, 1));
        v1m = fmaxf(v1m, __shfl_xor_sync(0xffffffffu, v1m, 2));
        if ((pg & 3) == 0) {
            long long q = (long long)(b*NPTS + n0 + nl);
            g_x1[q*64 + o0]     = v0m;
            g_x1[q*64 + o0 + 1] = v1m;
        }
    }
    __syncthreads();
    for (int l = tid; l < 1024; l += 128)
        ((float4*)(g_out1 + (long long)blockIdx.x*4096))[l] = ((const float4*)(sm + S1B))[l];
}

// =====================================================================
// Stage 2: 128-pos tiles, 256 thr, 2 CTAs/SM — R11 tiling, ping-pong
// weight buffers (ONE barrier per chunk).
// smem: B1 0, B2 8192, B3 16384, SW0 24576, SW1 25600, SX 26624
// =====================================================================
#define T2B1  0
#define T2B2  8192
#define T2B3  16384
#define T2SW0 24576
#define T2SW1 25600
#define T2SX  26624
#define T2_FLOATS 27136   // 108544 B -> 2 CTAs/SM

template<int KFULL>
__device__ __forceinline__ void ldgA2(float4& r, const float* __restrict__ src,
                                      int koff, int tid)
{
    int o = tid & 63, k4 = tid >> 6;
    r = *(const float4*)(src + o*KFULL + koff + 4*k4);
}
__device__ __forceinline__ void stsA2(float* __restrict__ dst, const float4& r, int tid)
{
    int o = tid & 63, k = (tid >> 6)*4;
    dst[(k  )*64+o] = r.x; dst[(k+1)*64+o] = r.y;
    dst[(k+2)*64+o] = r.z; dst[(k+3)*64+o] = r.w;
}
template<int KFULL>
__device__ __forceinline__ void ldgB2(float4& r, const float* __restrict__ src,
                                      int koff, int tid)
{
    int o = tid & 127, k4 = tid >> 7;
    r = *(const float4*)(src + o*KFULL + koff + 4*k4);
}
__device__ __forceinline__ void stsB2(float* __restrict__ dst, const float4& r, int tid)
{
    int o = tid & 127, k = (tid >> 7)*4;
    dst[(k  )*128+o] = r.x; dst[(k+1)*128+o] = r.y;
    dst[(k+2)*128+o] = r.z; dst[(k+3)*128+o] = r.w;
}

// 8 out (4 pairs) x 4 pos, 16-k chunk. w stride 64, act stride 128.
__device__ __forceinline__ void gemm8d(const float* __restrict__ w,
                                       const float* __restrict__ a,
                                       int og, int pg, u64 acc[4][4])
{
#pragma unroll
    for (int k = 0; k < 16; k++) {
        const float* wr = w + k*64 + og*8;
        ulonglong2 w01 = *(const ulonglong2*)wr;
        ulonglong2 w23 = *(const ulonglong2*)(wr+4);
        u64 wp[4] = {w01.x,w01.y,w23.x,w23.y};
        float4 av = *(const float4*)(a + k*128 + pg*4);
        u64 as[4] = {pk2(av.x,av.x), pk2(av.y,av.y), pk2(av.z,av.z), pk2(av.w,av.w)};
#pragma unroll
        for (int op = 0; op < 4; op++)
#pragma unroll
            for (int p = 0; p < 4; p++) fma2(acc[op][p], wp[op], as[p]);
    }
}

// 16 out (8 pairs) x 4 pos, 8-k chunk. w stride 128, act stride 128.
__device__ __forceinline__ void gemm16d(const float* __restrict__ w,
                                        const float* __restrict__ a,
                                        int og, int pg, u64 acc[8][4])
{
#pragma unroll
    for (int k = 0; k < 8; k++) {
        const float* wr = w + k*128 + og*16;
        ulonglong2 w01 = *(const ulonglong2*)wr;
        ulonglong2 w23 = *(const ulonglong2*)(wr+4);
        ulonglong2 w45 = *(const ulonglong2*)(wr+8);
        ulonglong2 w67 = *(const ulonglong2*)(wr+12);
        u64 wp[8] = {w01.x,w01.y,w23.x,w23.y,w45.x,w45.y,w67.x,w67.y};
        float4 av = *(const float4*)(a + k*128 + pg*4);
        u64 as[4] = {pk2(av.x,av.x), pk2(av.y,av.y), pk2(av.z,av.z), pk2(av.w,av.w)};
#pragma unroll
        for (int op = 0; op < 8; op++)
#pragma unroll
            for (int p = 0; p < 4; p++) fma2(acc[op][p], wp[op], as[p]);
    }
}

__global__ void __launch_bounds__(256,2) stage2_kernel(
    const float* __restrict__ w2sc, const float* __restrict__ b2sc,
    const float* __restrict__ w2a,  const float* __restrict__ b2a,
    const float* __restrict__ w2b,  const float* __restrict__ b2b,
    const float* __restrict__ w2c,  const float* __restrict__ b2c,
    float* __restrict__ outp)
{
    extern __shared__ float sm[];
    const int tid = threadIdx.x;
    const int og = tid >> 5, pg = tid & 31;
    const int nl = pg >> 2;
    const int base = blockIdx.x << 7;
    const int b  = base >> 17;
    const int nb = (base & (NPTS*KNB - 1)) >> 4;

    float* const W[2] = { sm + T2SW0, sm + T2SW1 };
    float4 R;

    // ---- prologue: chunk0 -> W0 ; B1/x1 loads ----
    ldgA2<128>(R, w2a, 0, tid);
    {
        const float4* src = (const float4*)(g_out1 + (long long)blockIdx.x*8192);
        for (int l = tid; l < 2048; l += 256) {
            int t = l >> 10, i = l & 1023;
            int ch = i >> 4, p4 = i & 15;
            *(float4*)(sm + T2B1 + ch*128 + t*64 + p4*4) = src[l];
        }
    }
    for (int l = tid; l < 512; l += 256) {
        int ch = l >> 3, q = l & 7;
        sm[T2SX + ch*8 + q] = g_x1[(long long)(b*NPTS + nb + q)*64 + ch];
    }
    stsA2(W[0], R, tid);
    __syncthreads();

    // step macro: ldg chunk c+1, gemm chunk c from W[c&1], sts -> W[1-(c&1)], 1 barrier
    u64 acc4[4][4];
#define ZERO4B {_Pragma("unroll") for (int op=0;op<4;op++) _Pragma("unroll") for (int p=0;p<4;p++) acc4[op][p]=0ull;}

    // ---- chunks 0..3: a main (A-type) on B1 ----
    ZERO4B
#pragma unroll
    for (int c = 0; c < 4; c++) {
        if (c < 3) ldgA2<128>(R, w2a, (c+1)*16, tid);
        else       ldgA2<128>(R, w2a, 64, tid);          // chunk 4
        gemm8d(W[c&1], sm + T2B1 + c*16*128, og, pg, acc4);
        stsA2(W[1-(c&1)], R, tid);
        __syncthreads();
    }

    // ---- chunks 4..7: a x1-corr (A-type) ----
    u64 crA[4] = {0,0,0,0};
#define CORRA(BUF, C0) \
    _Pragma("unroll") \
    for (int cc = 0; cc < 16; cc++) { \
        const float* wr = (BUF) + cc*64 + og*8; \
        ulonglong2 w01 = *(const ulonglong2*)wr; \
        ulonglong2 w23 = *(const ulonglong2*)(wr+4); \
        float xv = sm[T2SX + ((C0)+cc)*8 + nl]; \
        u64 xs = pk2(xv, xv); \
        fma2(crA[0], w01.x, xs); fma2(crA[1], w01.y, xs); \
        fma2(crA[2], w23.x, xs); fma2(crA[3], w23.y, xs); \
    }
#pragma unroll
    for (int c = 4; c < 8; c++) {
        if (c < 7) ldgA2<128>(R, w2a, 64 + (c-3)*16, tid);
        else       ldgB2<64>(R, w2b, 0, tid);             // chunk 8
        CORRA(W[c&1], (c-4)*16)
        if (c < 7) stsA2(W[1-(c&1)], R, tid);
        else       stsB2(W[1-(c&1)], R, tid);
        __syncthreads();
    }
    // a epilogue: h -> B2
#pragma unroll
    for (int op=0;op<4;op++) {
        int o0 = og*8 + 2*op;
        float2 c2 = up2(crA[op]);
        float b0 = __ldg(b2a + o0) + c2.x;
        float b1 = __ldg(b2a + o0 + 1) + c2.y;
#pragma unroll
        for (int p=0;p<4;p++) {
            float2 v = up2(acc4[op][p]);
            sm[T2B2 + (o0  )*128 + pg*4 + p] = leaky(v.x + b0);
            sm[T2B2 + (o0+1)*128 + pg*4 + p] = leaky(v.y + b1);
        }
    }
    __syncthreads();

    // ---- chunks 8..15: b (B-type) on B2(h) ----
    u64 acc[8][4];
#pragma unroll
    for (int op=0;op<8;op++)
#pragma unroll
        for (int p=0;p<4;p++) acc[op][p]=0ull;
#pragma unroll
    for (int c = 8; c < 16; c++) {
        if (c < 15) ldgB2<64>(R, w2b, (c-7)*8, tid);
        else        ldgB2<128>(R, w2c, 0, tid);           // chunk 16
        gemm16d(W[c&1], sm + T2B2 + (c-8)*1024, og, pg, acc);
        stsB2(W[1-(c&1)], R, tid);
        __syncthreads();
    }
    // h2 epilogue: ch<64 -> B3, ch>=64 -> B2
#pragma unroll
    for (int op=0;op<8;op++) {
        int o0 = og*16 + 2*op;
        float b0 = __ldg(b2b + o0), b1 = __ldg(b2b + o0+1);
        float* d0 = sm + ((o0 < 64) ? (T2B3 + o0*128) : (T2B2 + (o0-64)*128));
        float* d1 = sm + ((o0+1 < 64) ? (T2B3 + (o0+1)*128) : (T2B2 + (o0+1-64)*128));
#pragma unroll
        for (int p=0;p<4;p++) {
            float2 v = up2(acc[op][p]);
            d0[pg*4 + p] = leaky(v.x + b0);
            d1[pg*4 + p] = leaky(v.y + b1);
        }
    }
    __syncthreads();

    // ---- chunks 16..39: c lo (B3), c hi (B2), sc main (B1) ----
#pragma unroll
    for (int op=0;op<8;op++)
#pragma unroll
        for (int p=0;p<4;p++) acc[op][p]=0ull;
#pragma unroll
    for (int c = 16; c < 24; c++) {
        if (c < 23) ldgB2<128>(R, w2c, (c-15)*8, tid);
        else        ldgB2<128>(R, w2c, 64, tid);          // chunk 24
        gemm16d(W[c&1], sm + T2B3 + (c-16)*1024, og, pg, acc);
        stsB2(W[1-(c&1)], R, tid);
        __syncthreads();
    }
#pragma unroll
    for (int c = 24; c < 32; c++) {
        if (c < 31) ldgB2<128>(R, w2c, 64 + (c-23)*8, tid);
        else        ldgB2<128>(R, w2sc, 0, tid);          // chunk 32
        gemm16d(W[c&1], sm + T2B2 + (c-24)*1024, og, pg, acc);
        stsB2(W[1-(c&1)], R, tid);
        __syncthreads();
    }
#pragma unroll
    for (int c = 32; c < 40; c++) {
        if (c < 39) ldgB2<128>(R, w2sc, (c-31)*8, tid);
        else        ldgB2<128>(R, w2sc, 64, tid);         // chunk 40
        gemm16d(W[c&1], sm + T2B1 + (c-32)*1024, og, pg, acc);
        stsB2(W[1-(c&1)], R, tid);
        __syncthreads();
    }

    // ---- chunks 40..47: sc x1-corr ----
    u64 cr2[8] = {0,0,0,0,0,0,0,0};
#define CORRS(BUF, C0) \
    _Pragma("unroll") \
    for (int cc = 0; cc < 8; cc++) { \
        const float* wr = (BUF) + cc*128 + og*16; \
        ulonglong2 w01 = *(const ulonglong2*)wr; \
        ulonglong2 w23 = *(const ulonglong2*)(wr+4); \
        ulonglong2 w45 = *(const ulonglong2*)(wr+8); \
        ulonglong2 w67 = *(const ulonglong2*)(wr+12); \
        float xv = sm[T2SX + ((C0)+cc)*8 + nl]; \
        u64 xs = pk2(xv, xv); \
        fma2(cr2[0], w01.x, xs); fma2(cr2[1], w01.y, xs); \
        fma2(cr2[2], w23.x, xs); fma2(cr2[3], w23.y, xs); \
        fma2(cr2[4], w45.x, xs); fma2(cr2[5], w45.y, xs); \
        fma2(cr2[6], w67.x, xs); fma2(cr2[7], w67.y, xs); \
    }
#pragma unroll
    for (int c = 40; c < 47; c++) {
        ldgB2<128>(R, w2sc, 64 + (c-39)*8, tid);
        CORRS(W[c&1], (c-40)*8)
        stsB2(W[1-(c&1)], R, tid);
        __syncthreads();
    }
    CORRS(W[1], 56)   // chunk 47 (odd)

    // ---- final epilogue ----
#pragma unroll
    for (int op=0;op<8;op++) {
        int o0 = og*16 + 2*op;
        float2 c2 = up2(cr2[op]);
        float bt0 = __ldg(b2sc + o0)     + __ldg(b2c + o0)     + c2.x;
        float bt1 = __ldg(b2sc + o0 + 1) + __ldg(b2c + o0 + 1) + c2.y;
        float m0 = -3.4e38f, m1 = -3.4e38f;
#pragma unroll
        for (int p=0;p<4;p++) {
            float2 v = up2(acc[op][p]);
            m0 = fmaxf(m0, v.x); m1 = fmaxf(m1, v.y);
        }
        m0 += bt0; m1 += bt1;
        m0 = fmaxf(m0, __shfl_xor_sync(0xffffffffu, m0, 1));
        m0 = fmaxf(m0, __shfl_xor_sync(0xffffffffu, m0, 2));
        m1 = fmaxf(m1, __shfl_xor_sync(0xffffffffu, m1, 1));
        m1 = fmaxf(m1, __shfl_xor_sync(0xffffffffu, m1, 2));
        if ((pg & 3) == 0) {
            outp[((long long)b*128 + o0    )*NPTS + nb + nl] = m0;
            outp[((long long)b*128 + o0 + 1)*NPTS + nb + nl] = m1;
        }
    }
}

// =====================================================================
extern "C" void kernel_launch(void* const* d_in, const int* in_sizes, int n_in,
                              void* d_out, int out_size)
{
    const float* xyz     = (const float*)d_in[0];
    const float* p1_sc_w = (const float*)d_in[1];
    const float* p1_sc_b = (const float*)d_in[2];
    const float* p1_a_w  = (const float*)d_in[3];
    const float* p1_a_b  = (const float*)d_in[4];
    const float* p1_b_w  = (const float*)d_in[5];
    const float* p1_b_b  = (const float*)d_in[6];
    const float* p1_c_w  = (const float*)d_in[7];
    const float* p1_c_b  = (const float*)d_in[8];
    const float* p2_sc_w = (const float*)d_in[9];
    const float* p2_sc_b = (const float*)d_in[10];
    const float* p2_a_w  = (const float*)d_in[11];
    const float* p2_a_b  = (const float*)d_in[12];
    const float* p2_b_w  = (const float*)d_in[13];
    const float* p2_b_b  = (const float*)d_in[14];
    const float* p2_c_w  = (const float*)d_in[15];
    const float* p2_c_b  = (const float*)d_in[16];
    float* outp = (float*)d_out;

    cudaFuncSetAttribute(stage1_kernel, cudaFuncAttributeMaxDynamicSharedMemorySize,
                         S1_FLOATS*4);
    cudaFuncSetAttribute(stage2_kernel, cudaFuncAttributeMaxDynamicSharedMemorySize,
                         T2_FLOATS*4);

    knn_part<<<512, 128, 32768>>>(xyz);
    knn_merge<<<NQ/256, 256>>>();
    stage1_kernel<<<NPOS/64, 128, S1_FLOATS*4>>>(
        xyz, p1_sc_w, p1_sc_b, p1_a_w, p1_a_b, p1_b_w, p1_b_b, p1_c_w, p1_c_b);
    stage2_kernel<<<NPOS/128, 256, T2_FLOATS*4>>>(
        p2_sc_w, p2_sc_b, p2_a_w, p2_a_b, p2_b_w, p2_b_b, p2_c_w, p2_c_b, outp);
}

// round 14
// speedup vs baseline: 1.1681x; 1.0285x over previous
#include <cuda_runtime.h>
#include <math.h>

#define BATCH 4
#define NPTS  8192
#define KNB   16
#define NPOS  (BATCH*NPTS*KNB)   // 524288
#define NQ    (BATCH*NPTS)       // 32768
#define CAP   48
#define NPART 4

__device__ int g_idx[NQ*KNB];
__device__ unsigned long long g_sbuf[(long long)NQ*NPART*CAP];
__device__ int g_scnt[NQ*NPART];
__device__ float g_out1[(long long)NPOS*64];   // 134 MB
__device__ float g_x1[(long long)NQ*64];       // 8 MB
__device__ float g_corr[(long long)NQ*192];    // 25 MB

typedef unsigned long long u64;

__device__ __forceinline__ u64 pk2(float x, float y) {
    u64 r; asm("mov.b64 %0,{%1,%2};" : "=l"(r) : "f"(x), "f"(y)); return r;
}
__device__ __forceinline__ float2 up2(u64 v) {
    float2 r; asm("mov.b64 {%0,%1},%2;" : "=f"(r.x), "=f"(r.y) : "l"(v)); return r;
}
__device__ __forceinline__ void fma2(u64& d, u64 a, u64 b) {
    asm("fma.rn.f32x2 %0,%1,%2,%0;" : "+l"(d) : "l"(a), "l"(b));
}
__device__ __forceinline__ float leaky(float v) { return v >= 0.f ? v : 0.2f*v; }

// =====================================================================
// KNN (unchanged)
// =====================================================================
__device__ __forceinline__ void bitonic32(float s[32]) {
#pragma unroll
    for (int k = 2; k <= 32; k <<= 1) {
#pragma unroll
        for (int j = k >> 1; j > 0; j >>= 1) {
#pragma unroll
            for (int ii = 0; ii < 32; ii++) {
                int l = ii ^ j;
                if (l > ii) {
                    float lo = fminf(s[ii], s[l]);
                    float hi = fmaxf(s[ii], s[l]);
                    bool up = ((ii & k) == 0);
                    s[ii] = up ? lo : hi;
                    s[l]  = up ? hi : lo;
                }
            }
        }
    }
}

__device__ __forceinline__ void exact16(const float4* tile, float x2, float y2,
                                        float z2, int c0, u64 buf[16]) {
    float bd[16]; int bj[16];
#pragma unroll
    for (int t = 0; t < 16; t++) { bd[t] = 3.4e38f; bj[t] = 0; }
    float cm = 3.4e38f;
    for (int j = 0; j < 2048; j++) {
        float4 p = tile[j];
        float d = fmaf(x2, p.x, fmaf(y2, p.y, fmaf(z2, p.z, p.w)));
        if (d < cm) {
            int am = 0; float mv = bd[0];
#pragma unroll
            for (int u = 1; u < 16; u++) if (bd[u] > mv) { mv = bd[u]; am = u; }
#pragma unroll
            for (int u = 0; u < 16; u++) if (u == am) { bd[u] = d; bj[u] = c0 + j; }
            cm = bd[0];
#pragma unroll
            for (int u = 1; u < 16; u++) cm = fmaxf(cm, bd[u]);
        }
    }
#pragma unroll
    for (int t = 0; t < 16; t++) buf[t] = pk2(bd[t], __int_as_float(bj[t]));
}

__global__ __launch_bounds__(128) void knn_part(const float* __restrict__ xyz)
{
    extern __shared__ float4 tile[];
    const int tid = threadIdx.x;
    const int quarter = blockIdx.x & 3;
    const int qb = (blockIdx.x >> 2) & 31;
    const int b  = blockIdx.x >> 7;
    const int i0 = qb*256 + tid;
    const int i1 = i0 + 128;
    const float* xb = xyz + b*3*NPTS;
    const int c0 = quarter*2048;

    for (int l = tid; l < 512; l += 128) {
        float4 vx = ((const float4*)(xb + c0))[l];
        float4 vy = ((const float4*)(xb + NPTS + c0))[l];
        float4 vz = ((const float4*)(xb + 2*NPTS + c0))[l];
        tile[4*l+0] = make_float4(vx.x, vy.x, vz.x, fmaf(vx.x,vx.x, fmaf(vy.x,vy.x, vz.x*vz.x)));
        tile[4*l+1] = make_float4(vx.y, vy.y, vz.y, fmaf(vx.y,vx.y, fmaf(vy.y,vy.y, vz.y*vz.y)));
        tile[4*l+2] = make_float4(vx.z, vy.z, vz.z, fmaf(vx.z,vx.z, fmaf(vy.z,vy.z, vz.z*vz.z)));
        tile[4*l+3] = make_float4(vx.w, vy.w, vz.w, fmaf(vx.w,vx.w, fmaf(vy.w,vy.w, vz.w*vz.w)));
    }
    __syncthreads();

    const float x20 = -2.0f*xb[i0], y20 = -2.0f*xb[NPTS+i0], z20 = -2.0f*xb[2*NPTS+i0];
    const float x21 = -2.0f*xb[i1], y21 = -2.0f*xb[NPTS+i1], z21 = -2.0f*xb[2*NPTS+i1];

    float s0[32], s1[32];
#pragma unroll
    for (int t = 0; t < 32; t++) { s0[t] = 3.4e38f; s1[t] = 3.4e38f; }
    for (int j0 = 0; j0 < 2048; j0 += 32) {
#pragma unroll
        for (int u = 0; u < 32; u++) {
            float4 p = tile[j0+u];
            float d0 = fmaf(x20, p.x, fmaf(y20, p.y, fmaf(z20, p.z, p.w)));
            float d1 = fmaf(x21, p.x, fmaf(y21, p.y, fmaf(z21, p.z, p.w)));
            s0[u] = fminf(s0[u], d0);
            s1[u] = fminf(s1[u], d1);
        }
    }

    bitonic32(s0);
    bitonic32(s1);
    const float T0 = s0[15], T1 = s1[15];

    u64 buf0[CAP], buf1[CAP];
    int cnt0 = 0, cnt1 = 0, ovf0 = 0, ovf1 = 0;
    for (int j = 0; j < 2048; j++) {
        float4 p = tile[j];
        float d0 = fmaf(x20, p.x, fmaf(y20, p.y, fmaf(z20, p.z, p.w)));
        float d1 = fmaf(x21, p.x, fmaf(y21, p.y, fmaf(z21, p.z, p.w)));
        if (d0 <= T0) {
            if (cnt0 < CAP) { buf0[cnt0] = pk2(d0, __int_as_float(c0+j)); cnt0++; }
            else ovf0 = 1;
        }
        if (d1 <= T1) {
            if (cnt1 < CAP) { buf1[cnt1] = pk2(d1, __int_as_float(c0+j)); cnt1++; }
            else ovf1 = 1;
        }
    }

    if (ovf0) { exact16(tile, x20, y20, z20, c0, buf0); cnt0 = 16; }
    if (ovf1) { exact16(tile, x21, y21, z21, c0, buf1); cnt1 = 16; }

    {
        const int qg = b*NPTS + i0;
        g_scnt[qg*NPART + quarter] = cnt0;
        u64* dst = g_sbuf + (long long)(qg*NPART + quarter)*CAP;
        for (int t = 0; t < cnt0; t++) dst[t] = buf0[t];
    }
    {
        const int qg = b*NPTS + i1;
        g_scnt[qg*NPART + quarter] = cnt1;
        u64* dst = g_sbuf + (long long)(qg*NPART + quarter)*CAP;
        for (int t = 0; t < cnt1; t++) dst[t] = buf1[t];
    }
}

__global__ __launch_bounds__(256) void knn_merge()
{
    const int q = blockIdx.x*256 + threadIdx.x;
    float bd[16]; int bj[16];
#pragma unroll
    for (int t = 0; t < 16; t++) { bd[t] = 3.4e38f; bj[t] = 0; }
    float cm = 3.4e38f;
#pragma unroll
    for (int h = 0; h < NPART; h++) {
        const int c = g_scnt[q*NPART + h];
        const u64* src = g_sbuf + (long long)(q*NPART + h)*CAP;
        for (int e = 0; e < c; e++) {
            float2 v = up2(src[e]);
            float d = v.x;
            if (d < cm) {
                int am = 0; float mv = bd[0];
#pragma unroll
                for (int u = 1; u < 16; u++) if (bd[u] > mv) { mv = bd[u]; am = u; }
#pragma unroll
                for (int u = 0; u < 16; u++) if (u == am) { bd[u] = d; bj[u] = __float_as_int(v.y); }
                cm = bd[0];
#pragma unroll
                for (int u = 1; u < 16; u++) cm = fmaxf(cm, bd[u]);
            }
        }
    }
#pragma unroll
    for (int t = 0; t < 16; t++) g_idx[q*16 + t] = bj[t];
}

// =====================================================================
// Stage 1 (unchanged): 64-pos tiles, 128 thr, 4 CTAs/SM
// =====================================================================
#define S1A 0
#define S1B 4096
#define S1C 8192
#define S1W 12288
#define S1_FLOATS 13312

template<int KFULL>
__device__ __forceinline__ void ldgA16(float4 r[2], const float* __restrict__ src,
                                       int koff, int tid)
{
#pragma unroll
    for (int it = 0; it < 2; it++) {
        int l = it*128 + tid;
        int o = l & 63, k4 = l >> 6;
        r[it] = *(const float4*)(src + o*KFULL + koff + 4*k4);
    }
}
__device__ __forceinline__ void stsA16(float* __restrict__ dst, const float4 r[2], int tid)
{
#pragma unroll
    for (int it = 0; it < 2; it++) {
        int l = it*128 + tid;
        int o = l & 63, k = (l >> 6)*4;
        dst[(k  )*64+o] = r[it].x; dst[(k+1)*64+o] = r[it].y;
        dst[(k+2)*64+o] = r[it].z; dst[(k+3)*64+o] = r[it].w;
    }
}

__device__ __forceinline__ void gemm8c(const float* __restrict__ w,
                                       const float* __restrict__ a,
                                       int og, int pg, u64 acc[4][4])
{
#pragma unroll
    for (int k = 0; k < 16; k++) {
        const float* wr = w + k*64 + og*8;
        ulonglong2 w01 = *(const ulonglong2*)wr;
        ulonglong2 w23 = *(const ulonglong2*)(wr+4);
        u64 wp[4] = {w01.x,w01.y,w23.x,w23.y};
        float4 av = *(const float4*)(a + k*64 + pg*4);
        u64 as[4] = {pk2(av.x,av.x), pk2(av.y,av.y), pk2(av.z,av.z), pk2(av.w,av.w)};
#pragma unroll
        for (int op = 0; op < 4; op++)
#pragma unroll
            for (int p = 0; p < 4; p++) fma2(acc[op][p], wp[op], as[p]);
    }
}

__global__ void __launch_bounds__(128,4) stage1_kernel(
    const float* __restrict__ xyz,
    const float* __restrict__ w1sc, const float* __restrict__ b1sc,
    const float* __restrict__ w1a,  const float* __restrict__ b1a,
    const float* __restrict__ w1b,  const float* __restrict__ b1b,
    const float* __restrict__ w1c,  const float* __restrict__ b1c)
{
    extern __shared__ float sm[];
    const int tid = threadIdx.x;
    const int pg = tid & 15, og = tid >> 4;
    const int base = blockIdx.x << 6;
    const int b  = base >> 17;
    const int n0 = (base & (NPTS*KNB - 1)) >> 4;
    const int nl = pg >> 2;

    float4 R[2];

    ldgA16<64>(R, w1b, 0, tid);
    for (int l = tid; l < 640; l += 128) {
        int o = l/10, k = l - o*10;
        sm[S1C + 640  + k*64 + o] = w1sc[l];
        sm[S1C + 1280 + k*64 + o] = w1a[l];
    }
    if (tid < 64) {
        int nn = n0 + (tid >> 4);
        const float* xb = xyz + b*3*NPTS;
        int j = g_idx[(b*NPTS + nn)*KNB + (tid & 15)];
        float cx = xb[nn], cy = xb[NPTS+nn], cz = xb[2*NPTS+nn];
        float nx = xb[j],  ny = xb[NPTS+j],  nz = xb[2*NPTS+j];
        float rx = nx-cx, ry = ny-cy, rz = nz-cz;
        float dd = sqrtf(fmaf(rx,rx, fmaf(ry,ry, rz*rz)) + 1e-12f);
        sm[S1C+0*64+tid]=cx; sm[S1C+1*64+tid]=cy; sm[S1C+2*64+tid]=cz;
        sm[S1C+3*64+tid]=nx; sm[S1C+4*64+tid]=ny; sm[S1C+5*64+tid]=nz;
        sm[S1C+6*64+tid]=rx; sm[S1C+7*64+tid]=ry; sm[S1C+8*64+tid]=rz;
        sm[S1C+9*64+tid]=dd;
    }
    __syncthreads();
    stsA16(sm + S1W, R, tid);
    ldgA16<64>(R, w1b, 16, tid);

    {
        u64 accS[4][4], accA[4][4];
#pragma unroll
        for (int op=0;op<4;op++)
#pragma unroll
            for (int p=0;p<4;p++) { accS[op][p]=0ull; accA[op][p]=0ull; }
#pragma unroll
        for (int k = 0; k < 10; k++) {
            const float* wsr = sm + S1C + 640  + k*64 + og*8;
            const float* war = sm + S1C + 1280 + k*64 + og*8;
            ulonglong2 ws01 = *(const ulonglong2*)wsr;
            ulonglong2 ws23 = *(const ulonglong2*)(wsr+4);
            ulonglong2 wa01 = *(const ulonglong2*)war;
            ulonglong2 wa23 = *(const ulonglong2*)(war+4);
            u64 wsp[4] = {ws01.x,ws01.y,ws23.x,ws23.y};
            u64 wap[4] = {wa01.x,wa01.y,wa23.x,wa23.y};
            float4 av = *(const float4*)(sm + S1C + k*64 + pg*4);
            u64 as[4] = {pk2(av.x,av.x), pk2(av.y,av.y), pk2(av.z,av.z), pk2(av.w,av.w)};
#pragma unroll
            for (int op=0;op<4;op++)
#pragma unroll
                for (int p=0;p<4;p++) { fma2(accS[op][p], wsp[op], as[p]); fma2(accA[op][p], wap[op], as[p]); }
        }
#pragma unroll
        for (int op=0;op<4;op++) {
            int o0 = og*8 + 2*op;
            float ba0 = __ldg(b1a + o0), ba1 = __ldg(b1a + o0 + 1);
#pragma unroll
            for (int p=0;p<4;p++) {
                float2 va = up2(accA[op][p]);
                sm[S1A + (o0  )*64 + pg*4 + p] = leaky(va.x + ba0);
                sm[S1A + (o0+1)*64 + pg*4 + p] = leaky(va.y + ba1);
                float2 vs = up2(accS[op][p]);
                sm[S1B + (o0  )*64 + pg*4 + p] = vs.x;
                sm[S1B + (o0+1)*64 + pg*4 + p] = vs.y;
            }
        }
    }
    __syncthreads();

    u64 acc4[4][4];
#define ZERO4 {_Pragma("unroll") for (int op=0;op<4;op++) _Pragma("unroll") for (int p=0;p<4;p++) acc4[op][p]=0ull;}
#define PUMP1(STSF)  { __syncthreads(); STSF(sm + S1W, R, tid); __syncthreads(); }

    ZERO4
#pragma unroll 1
    for (int c = 0; c < 3; c++) {
        if (c > 0) ldgA16<64>(R, w1b, (c+1)*16, tid);
        gemm8c(sm + S1W, sm + S1A + c*1024, og, pg, acc4);
        PUMP1(stsA16)
    }
    ldgA16<64>(R, w1c, 0, tid);
    gemm8c(sm + S1W, sm + S1A + 3*1024, og, pg, acc4);
    PUMP1(stsA16)
#pragma unroll
    for (int op=0;op<4;op++) {
        int o0 = og*8 + 2*op;
        float b0 = __ldg(b1b + o0), b1 = __ldg(b1b + o0 + 1);
#pragma unroll
        for (int p=0;p<4;p++) {
            float2 v = up2(acc4[op][p]);
            sm[S1C + (o0  )*64 + pg*4 + p] = leaky(v.x + b0);
            sm[S1C + (o0+1)*64 + pg*4 + p] = leaky(v.y + b1);
        }
    }
    __syncthreads();

    ZERO4
#pragma unroll 1
    for (int c = 0; c < 3; c++) {
        ldgA16<64>(R, w1c, (c+1)*16, tid);
        gemm8c(sm + S1W, sm + S1C + c*1024, og, pg, acc4);
        PUMP1(stsA16)
    }
    gemm8c(sm + S1W, sm + S1C + 3*1024, og, pg, acc4);
#pragma unroll
    for (int op=0;op<4;op++) {
        int o0 = og*8 + 2*op;
        float bt0 = __ldg(b1c + o0)     + __ldg(b1sc + o0);
        float bt1 = __ldg(b1c + o0 + 1) + __ldg(b1sc + o0 + 1);
        float v0m = -3.4e38f, v1m = -3.4e38f;
#pragma unroll
        for (int p=0;p<4;p++) {
            float2 v = up2(acc4[op][p]);
            float o0v = v.x + sm[S1B + (o0  )*64 + pg*4 + p] + bt0;
            float o1v = v.y + sm[S1B + (o0+1)*64 + pg*4 + p] + bt1;
            sm[S1B + (o0  )*64 + pg*4 + p] = o0v;
            sm[S1B + (o0+1)*64 + pg*4 + p] = o1v;
            v0m = fmaxf(v0m, o0v); v1m = fmaxf(v1m, o1v);
        }
        v0m = fmaxf(v0m, __shfl_xor_sync(0xffffffffu, v0m, 1));
        v0m = fmaxf(v0m, __shfl_xor_sync(0xffffffffu, v0m, 2));
        v1m = fmaxf(v1m, __shfl_xor_sync(0xffffffffu, v1m, 1));
        v1m = fmaxf(v1m, __shfl_xor_sync(0xffffffffu, v1m, 2));
        if ((pg & 3) == 0) {
            long long q = (long long)(b*NPTS + n0 + nl);
            g_x1[q*64 + o0]     = v0m;
            g_x1[q*64 + o0 + 1] = v1m;
        }
    }
    __syncthreads();
    for (int l = tid; l < 1024; l += 128)
        ((float4*)(g_out1 + (long long)blockIdx.x*4096))[l] = ((const float4*)(sm + S1B))[l];
}

// =====================================================================
// Shared stage-2 gemm helpers (strides: weights 64/128, act 128)
// =====================================================================
__device__ __forceinline__ void gemm8d(const float* __restrict__ w,
                                       const float* __restrict__ a,
                                       int og, int pg, u64 acc[4][4])
{
#pragma unroll
    for (int k = 0; k < 16; k++) {
        const float* wr = w + k*64 + og*8;
        ulonglong2 w01 = *(const ulonglong2*)wr;
        ulonglong2 w23 = *(const ulonglong2*)(wr+4);
        u64 wp[4] = {w01.x,w01.y,w23.x,w23.y};
        float4 av = *(const float4*)(a + k*128 + pg*4);
        u64 as[4] = {pk2(av.x,av.x), pk2(av.y,av.y), pk2(av.z,av.z), pk2(av.w,av.w)};
#pragma unroll
        for (int op = 0; op < 4; op++)
#pragma unroll
            for (int p = 0; p < 4; p++) fma2(acc[op][p], wp[op], as[p]);
    }
}

__device__ __forceinline__ void gemm16d(const float* __restrict__ w,
                                        const float* __restrict__ a,
                                        int og, int pg, u64 acc[8][4])
{
#pragma unroll
    for (int k = 0; k < 8; k++) {
        const float* wr = w + k*128 + og*16;
        ulonglong2 w01 = *(const ulonglong2*)wr;
        ulonglong2 w23 = *(const ulonglong2*)(wr+4);
        ulonglong2 w45 = *(const ulonglong2*)(wr+8);
        ulonglong2 w67 = *(const ulonglong2*)(wr+12);
        u64 wp[8] = {w01.x,w01.y,w23.x,w23.y,w45.x,w45.y,w67.x,w67.y};
        float4 av = *(const float4*)(a + k*128 + pg*4);
        u64 as[4] = {pk2(av.x,av.x), pk2(av.y,av.y), pk2(av.z,av.z), pk2(av.w,av.w)};
#pragma unroll
        for (int op = 0; op < 8; op++)
#pragma unroll
            for (int p = 0; p < 4; p++) fma2(acc[op][p], wp[op], as[p]);
    }
}

// =====================================================================
// Corr kernel: corr_a[n,64] = w2a[:,64:]^T x1[n], corr_sc[n,128] likewise.
// 256 blocks x 256 thr; per block 128 n. smem 80KB.
// =====================================================================
#define CX 0        // X1T [64k][128n]  8192
#define CWA 8192    // WA  [64k][64o]   4096
#define CWS 12288   // WS  [64k][128o]  8192
#define C_FLOATS 20480

__global__ void __launch_bounds__(256) corr_kernel(
    const float* __restrict__ w2a, const float* __restrict__ w2sc)
{
    extern __shared__ float sm[];
    const int tid = threadIdx.x;
    const int og = tid >> 5, pg = tid & 31;
    const int nq0 = blockIdx.x*128;

    // x1 tile -> [k][n]
    for (int l = tid; l < 2048; l += 256) {
        int n = l >> 4, k4 = l & 15;
        float4 v = ((const float4*)(g_x1 + (long long)(nq0 + n)*64))[k4];
        sm[CX + (4*k4  )*128 + n] = v.x;
        sm[CX + (4*k4+1)*128 + n] = v.y;
        sm[CX + (4*k4+2)*128 + n] = v.z;
        sm[CX + (4*k4+3)*128 + n] = v.w;
    }
    // WA: w2a hi cols -> [k][o] stride 64
    for (int l = tid; l < 1024; l += 256) {
        int o = l & 63, k4 = l >> 6;
        float4 v = *(const float4*)(w2a + o*128 + 64 + 4*k4);
        sm[CWA + (4*k4  )*64 + o] = v.x;
        sm[CWA + (4*k4+1)*64 + o] = v.y;
        sm[CWA + (4*k4+2)*64 + o] = v.z;
        sm[CWA + (4*k4+3)*64 + o] = v.w;
    }
    // WS: w2sc hi cols -> [k][o] stride 128
    for (int l = tid; l < 2048; l += 256) {
        int o = l & 127, k4 = l >> 7;
        float4 v = *(const float4*)(w2sc + o*128 + 64 + 4*k4);
        sm[CWS + (4*k4  )*128 + o] = v.x;
        sm[CWS + (4*k4+1)*128 + o] = v.y;
        sm[CWS + (4*k4+2)*128 + o] = v.z;
        sm[CWS + (4*k4+3)*128 + o] = v.w;
    }
    __syncthreads();

    // corr_a: 64 out x 128 n (8x4 per thread)
    {
        u64 acc[4][4];
#pragma unroll
        for (int op=0;op<4;op++)
#pragma unroll
            for (int p=0;p<4;p++) acc[op][p]=0ull;
#pragma unroll
        for (int c = 0; c < 4; c++)
            gemm8d(sm + CWA + c*16*64, sm + CX + c*16*128, og, pg, acc);
#pragma unroll
        for (int op=0;op<4;op++) {
            int o0 = og*8 + 2*op;
#pragma unroll
            for (int p=0;p<4;p++) {
                float2 v = up2(acc[op][p]);
                long long n = nq0 + pg*4 + p;
                g_corr[n*192 + o0]     = v.x;
                g_corr[n*192 + o0 + 1] = v.y;
            }
        }
    }
    // corr_sc: 128 out x 128 n (16x4 per thread)
    {
        u64 acc[8][4];
#pragma unroll
        for (int op=0;op<8;op++)
#pragma unroll
            for (int p=0;p<4;p++) acc[op][p]=0ull;
#pragma unroll
        for (int c = 0; c < 8; c++)
            gemm16d(sm + CWS + c*8*128, sm + CX + c*8*128, og, pg, acc);
#pragma unroll
        for (int op=0;op<8;op++) {
            int o0 = og*16 + 2*op;
#pragma unroll
            for (int p=0;p<4;p++) {
                float2 v = up2(acc[op][p]);
                long long n = nq0 + pg*4 + p;
                g_corr[n*192 + 64 + o0]     = v.x;
                g_corr[n*192 + 64 + o0 + 1] = v.y;
            }
        }
    }
}

// =====================================================================
// Stage 2: 128-pos tiles, 256 thr, 2 CTAs/SM — 36 chunks, corr loaded.
// smem: B1 0, B2 8192, B3 16384, SW0 24576, SW1 25600, SXC 26624(1536)
// =====================================================================
#define T2B1  0
#define T2B2  8192
#define T2B3  16384
#define T2SW0 24576
#define T2SW1 25600
#define T2SX  26624
#define T2_FLOATS 28160   // 112640 B -> 2 CTAs/SM

template<int KFULL>
__device__ __forceinline__ void ldgA2(float4& r, const float* __restrict__ src,
                                      int koff, int tid)
{
    int o = tid & 63, k4 = tid >> 6;
    r = *(const float4*)(src + o*KFULL + koff + 4*k4);
}
__device__ __forceinline__ void stsA2(float* __restrict__ dst, const float4& r, int tid)
{
    int o = tid & 63, k = (tid >> 6)*4;
    dst[(k  )*64+o] = r.x; dst[(k+1)*64+o] = r.y;
    dst[(k+2)*64+o] = r.z; dst[(k+3)*64+o] = r.w;
}
template<int KFULL>
__device__ __forceinline__ void ldgB2(float4& r, const float* __restrict__ src,
                                      int koff, int tid)
{
    int o = tid & 127, k4 = tid >> 7;
    r = *(const float4*)(src + o*KFULL + koff + 4*k4);
}
__device__ __forceinline__ void stsB2(float* __restrict__ dst, const float4& r, int tid)
{
    int o = tid & 127, k = (tid >> 7)*4;
    dst[(k  )*128+o] = r.x; dst[(k+1)*128+o] = r.y;
    dst[(k+2)*128+o] = r.z; dst[(k+3)*128+o] = r.w;
}

__global__ void __launch_bounds__(256,2) stage2_kernel(
    const float* __restrict__ w2sc, const float* __restrict__ b2sc,
    const float* __restrict__ w2a,  const float* __restrict__ b2a,
    const float* __restrict__ w2b,  const float* __restrict__ b2b,
    const float* __restrict__ w2c,  const float* __restrict__ b2c,
    float* __restrict__ outp)
{
    extern __shared__ float sm[];
    const int tid = threadIdx.x;
    const int og = tid >> 5, pg = tid & 31;
    const int nl = pg >> 2;
    const int base = blockIdx.x << 7;
    const int b  = base >> 17;
    const int nb = (base & (NPTS*KNB - 1)) >> 4;

    float* const W[2] = { sm + T2SW0, sm + T2SW1 };
    float4 R;

    // ---- prologue: chunk0 -> W0 ; B1 + corr loads ----
    ldgA2<128>(R, w2a, 0, tid);
    {
        const float4* src = (const float4*)(g_out1 + (long long)blockIdx.x*8192);
        for (int l = tid; l < 2048; l += 256) {
            int t = l >> 10, i = l & 1023;
            int ch = i >> 4, p4 = i & 15;
            *(float4*)(sm + T2B1 + ch*128 + t*64 + p4*4) = src[l];
        }
    }
    for (int l = tid; l < 1536; l += 256) {
        int j = l >> 3, q = l & 7;
        sm[T2SX + j*8 + q] = g_corr[(long long)(b*NPTS + nb + q)*192 + j];
    }
    stsA2(W[0], R, tid);
    __syncthreads();

    u64 acc4[4][4];
#define ZERO4B {_Pragma("unroll") for (int op=0;op<4;op++) _Pragma("unroll") for (int p=0;p<4;p++) acc4[op][p]=0ull;}

    // ---- chunks 0..3: a main (A-type) on B1 ----
    ZERO4B
#pragma unroll
    for (int c = 0; c < 4; c++) {
        if (c < 3) { ldgA2<128>(R, w2a, (c+1)*16, tid); }
        else       { ldgB2<64>(R, w2b, 0, tid); }        // chunk 4
        gemm8d(W[c&1], sm + T2B1 + c*16*128, og, pg, acc4);
        if (c < 3) stsA2(W[1-(c&1)], R, tid);
        else       stsB2(W[1-(c&1)], R, tid);
        __syncthreads();
    }
    // a epilogue: h = leaky(acc + b2a + corr_a) -> B2
#pragma unroll
    for (int op=0;op<4;op++) {
        int o0 = og*8 + 2*op;
        float b0 = __ldg(b2a + o0)     + sm[T2SX + (o0  )*8 + nl];
        float b1 = __ldg(b2a + o0 + 1) + sm[T2SX + (o0+1)*8 + nl];
#pragma unroll
        for (int p=0;p<4;p++) {
            float2 v = up2(acc4[op][p]);
            sm[T2B2 + (o0  )*128 + pg*4 + p] = leaky(v.x + b0);
            sm[T2B2 + (o0+1)*128 + pg*4 + p] = leaky(v.y + b1);
        }
    }
    __syncthreads();

    // ---- chunks 4..11: b (B-type) on B2(h) ----
    u64 acc[8][4];
#pragma unroll
    for (int op=0;op<8;op++)
#pragma unroll
        for (int p=0;p<4;p++) acc[op][p]=0ull;
#pragma unroll
    for (int c = 4; c < 12; c++) {
        if (c < 11) ldgB2<64>(R, w2b, (c-3)*8, tid);
        else        ldgB2<128>(R, w2c, 0, tid);           // chunk 12
        gemm16d(W[c&1], sm + T2B2 + (c-4)*1024, og, pg, acc);
        stsB2(W[1-(c&1)], R, tid);
        __syncthreads();
    }
    // h2 epilogue: ch<64 -> B3, ch>=64 -> B2
#pragma unroll
    for (int op=0;op<8;op++) {
        int o0 = og*16 + 2*op;
        float b0 = __ldg(b2b + o0), b1 = __ldg(b2b + o0+1);
        float* d0 = sm + ((o0 < 64) ? (T2B3 + o0*128) : (T2B2 + (o0-64)*128));
        float* d1 = sm + ((o0+1 < 64) ? (T2B3 + (o0+1)*128) : (T2B2 + (o0+1-64)*128));
#pragma unroll
        for (int p=0;p<4;p++) {
            float2 v = up2(acc[op][p]);
            d0[pg*4 + p] = leaky(v.x + b0);
            d1[pg*4 + p] = leaky(v.y + b1);
        }
    }
    __syncthreads();

    // ---- chunks 12..35: c lo (B3), c hi (B2), sc main (B1) ----
#pragma unroll
    for (int op=0;op<8;op++)
#pragma unroll
        for (int p=0;p<4;p++) acc[op][p]=0ull;
#pragma unroll
    for (int c = 12; c < 20; c++) {
        if (c < 19) ldgB2<128>(R, w2c, (c-11)*8, tid);
        else        ldgB2<128>(R, w2c, 64, tid);          // chunk 20
        gemm16d(W[c&1], sm + T2B3 + (c-12)*1024, og, pg, acc);
        stsB2(W[1-(c&1)], R, tid);
        __syncthreads();
    }
#pragma unroll
    for (int c = 20; c < 28; c++) {
        if (c < 27) ldgB2<128>(R, w2c, 64 + (c-19)*8, tid);
        else        ldgB2<128>(R, w2sc, 0, tid);          // chunk 28
        gemm16d(W[c&1], sm + T2B2 + (c-20)*1024, og, pg, acc);
        stsB2(W[1-(c&1)], R, tid);
        __syncthreads();
    }
#pragma unroll
    for (int c = 28; c < 35; c++) {
        ldgB2<128>(R, w2sc, (c-27)*8, tid);
        gemm16d(W[c&1], sm + T2B1 + (c-28)*1024, og, pg, acc);
        stsB2(W[1-(c&1)], R, tid);
        __syncthreads();
    }
    gemm16d(W[1], sm + T2B1 + 7*1024, og, pg, acc);        // chunk 35 (odd)

    // ---- final epilogue: +biases +corr_sc, max over 16 k, write ----
#pragma unroll
    for (int op=0;op<8;op++) {
        int o0 = og*16 + 2*op;
        float bt0 = __ldg(b2sc + o0)     + __ldg(b2c + o0)     + sm[T2SX + (64+o0  )*8 + nl];
        float bt1 = __ldg(b2sc + o0 + 1) + __ldg(b2c + o0 + 1) + sm[T2SX + (64+o0+1)*8 + nl];
        float m0 = -3.4e38f, m1 = -3.4e38f;
#pragma unroll
        for (int p=0;p<4;p++) {
            float2 v = up2(acc[op][p]);
            m0 = fmaxf(m0, v.x); m1 = fmaxf(m1, v.y);
        }
        m0 += bt0; m1 += bt1;
        m0 = fmaxf(m0, __shfl_xor_sync(0xffffffffu, m0, 1));
        m0 = fmaxf(m0, __shfl_xor_sync(0xffffffffu, m0, 2));
        m1 = fmaxf(m1, __shfl_xor_sync(0xffffffffu, m1, 1));
        m1 = fmaxf(m1, __shfl_xor_sync(0xffffffffu, m1, 2));
        if ((pg & 3) == 0) {
            outp[((long long)b*128 + o0    )*NPTS + nb + nl] = m0;
            outp[((long long)b*128 + o0 + 1)*NPTS + nb + nl] = m1;
        }
    }
}

// =====================================================================
extern "C" void kernel_launch(void* const* d_in, const int* in_sizes, int n_in,
                              void* d_out, int out_size)
{
    const float* xyz     = (const float*)d_in[0];
    const float* p1_sc_w = (const float*)d_in[1];
    const float* p1_sc_b = (const float*)d_in[2];
    const float* p1_a_w  = (const float*)d_in[3];
    const float* p1_a_b  = (const float*)d_in[4];
    const float* p1_b_w  = (const float*)d_in[5];
    const float* p1_b_b  = (const float*)d_in[6];
    const float* p1_c_w  = (const float*)d_in[7];
    const float* p1_c_b  = (const float*)d_in[8];
    const float* p2_sc_w = (const float*)d_in[9];
    const float* p2_sc_b = (const float*)d_in[10];
    const float* p2_a_w  = (const float*)d_in[11];
    const float* p2_a_b  = (const float*)d_in[12];
    const float* p2_b_w  = (const float*)d_in[13];
    const float* p2_b_b  = (const float*)d_in[14];
    const float* p2_c_w  = (const float*)d_in[15];
    const float* p2_c_b  = (const float*)d_in[16];
    float* outp = (float*)d_out;

    cudaFuncSetAttribute(stage1_kernel, cudaFuncAttributeMaxDynamicSharedMemorySize,
                         S1_FLOATS*4);
    cudaFuncSetAttribute(corr_kernel, cudaFuncAttributeMaxDynamicSharedMemorySize,
                         C_FLOATS*4);
    cudaFuncSetAttribute(stage2_kernel, cudaFuncAttributeMaxDynamicSharedMemorySize,
                         T2_FLOATS*4);

    knn_part<<<512, 128, 32768>>>(xyz);
    knn_merge<<<NQ/256, 256>>>();
    stage1_kernel<<<NPOS/64, 128, S1_FLOATS*4>>>(
        xyz, p1_sc_w, p1_sc_b, p1_a_w, p1_a_b, p1_b_w, p1_b_b, p1_c_w, p1_c_b);
    corr_kernel<<<NQ/128, 256, C_FLOATS*4>>>(p2_a_w, p2_sc_w);
    stage2_kernel<<<NPOS/128, 256, T2_FLOATS*4>>>(
        p2_sc_w, p2_sc_b, p2_a_w, p2_a_b, p2_b_w, p2_b_b, p2_c_w, p2_c_b, outp);
}

// round 15
// speedup vs baseline: 1.1898x; 1.0186x over previous
#include <cuda_runtime.h>
#include <math.h>

#define BATCH 4
#define NPTS  8192
#define KNB   16
#define NPOS  (BATCH*NPTS*KNB)   // 524288
#define NQ    (BATCH*NPTS)       // 32768
#define CAP   48
#define NPART 4

__device__ int g_idx[NQ*KNB];
__device__ unsigned long long g_sbuf[(long long)NQ*NPART*CAP];
__device__ int g_scnt[NQ*NPART];
__device__ float g_out1[(long long)NPOS*64];   // 134 MB, [block][ch][pos] 128-pos blocks
__device__ float g_x1[(long long)NQ*64];       // 8 MB
__device__ float g_corr[(long long)NQ*192];    // 25 MB

typedef unsigned long long u64;

__device__ __forceinline__ u64 pk2(float x, float y) {
    u64 r; asm("mov.b64 %0,{%1,%2};" : "=l"(r) : "f"(x), "f"(y)); return r;
}
__device__ __forceinline__ float2 up2(u64 v) {
    float2 r; asm("mov.b64 {%0,%1},%2;" : "=f"(r.x), "=f"(r.y) : "l"(v)); return r;
}
__device__ __forceinline__ void fma2(u64& d, u64 a, u64 b) {
    asm("fma.rn.f32x2 %0,%1,%2,%0;" : "+l"(d) : "l"(a), "l"(b));
}
__device__ __forceinline__ float leaky(float v) { return v >= 0.f ? v : 0.2f*v; }

// =====================================================================
// KNN (unchanged)
// =====================================================================
__device__ __forceinline__ void bitonic32(float s[32]) {
#pragma unroll
    for (int k = 2; k <= 32; k <<= 1) {
#pragma unroll
        for (int j = k >> 1; j > 0; j >>= 1) {
#pragma unroll
            for (int ii = 0; ii < 32; ii++) {
                int l = ii ^ j;
                if (l > ii) {
                    float lo = fminf(s[ii], s[l]);
                    float hi = fmaxf(s[ii], s[l]);
                    bool up = ((ii & k) == 0);
                    s[ii] = up ? lo : hi;
                    s[l]  = up ? hi : lo;
                }
            }
        }
    }
}

__device__ __forceinline__ void exact16(const float4* tile, float x2, float y2,
                                        float z2, int c0, u64 buf[16]) {
    float bd[16]; int bj[16];
#pragma unroll
    for (int t = 0; t < 16; t++) { bd[t] = 3.4e38f; bj[t] = 0; }
    float cm = 3.4e38f;
    for (int j = 0; j < 2048; j++) {
        float4 p = tile[j];
        float d = fmaf(x2, p.x, fmaf(y2, p.y, fmaf(z2, p.z, p.w)));
        if (d < cm) {
            int am = 0; float mv = bd[0];
#pragma unroll
            for (int u = 1; u < 16; u++) if (bd[u] > mv) { mv = bd[u]; am = u; }
#pragma unroll
            for (int u = 0; u < 16; u++) if (u == am) { bd[u] = d; bj[u] = c0 + j; }
            cm = bd[0];
#pragma unroll
            for (int u = 1; u < 16; u++) cm = fmaxf(cm, bd[u]);
        }
    }
#pragma unroll
    for (int t = 0; t < 16; t++) buf[t] = pk2(bd[t], __int_as_float(bj[t]));
}

__global__ __launch_bounds__(128) void knn_part(const float* __restrict__ xyz)
{
    extern __shared__ float4 tile[];
    const int tid = threadIdx.x;
    const int quarter = blockIdx.x & 3;
    const int qb = (blockIdx.x >> 2) & 31;
    const int b  = blockIdx.x >> 7;
    const int i0 = qb*256 + tid;
    const int i1 = i0 + 128;
    const float* xb = xyz + b*3*NPTS;
    const int c0 = quarter*2048;

    for (int l = tid; l < 512; l += 128) {
        float4 vx = ((const float4*)(xb + c0))[l];
        float4 vy = ((const float4*)(xb + NPTS + c0))[l];
        float4 vz = ((const float4*)(xb + 2*NPTS + c0))[l];
        tile[4*l+0] = make_float4(vx.x, vy.x, vz.x, fmaf(vx.x,vx.x, fmaf(vy.x,vy.x, vz.x*vz.x)));
        tile[4*l+1] = make_float4(vx.y, vy.y, vz.y, fmaf(vx.y,vx.y, fmaf(vy.y,vy.y, vz.y*vz.y)));
        tile[4*l+2] = make_float4(vx.z, vy.z, vz.z, fmaf(vx.z,vx.z, fmaf(vy.z,vy.z, vz.z*vz.z)));
        tile[4*l+3] = make_float4(vx.w, vy.w, vz.w, fmaf(vx.w,vx.w, fmaf(vy.w,vy.w, vz.w*vz.w)));
    }
    __syncthreads();

    const float x20 = -2.0f*xb[i0], y20 = -2.0f*xb[NPTS+i0], z20 = -2.0f*xb[2*NPTS+i0];
    const float x21 = -2.0f*xb[i1], y21 = -2.0f*xb[NPTS+i1], z21 = -2.0f*xb[2*NPTS+i1];

    float s0[32], s1[32];
#pragma unroll
    for (int t = 0; t < 32; t++) { s0[t] = 3.4e38f; s1[t] = 3.4e38f; }
    for (int j0 = 0; j0 < 2048; j0 += 32) {
#pragma unroll
        for (int u = 0; u < 32; u++) {
            float4 p = tile[j0+u];
            float d0 = fmaf(x20, p.x, fmaf(y20, p.y, fmaf(z20, p.z, p.w)));
            float d1 = fmaf(x21, p.x, fmaf(y21, p.y, fmaf(z21, p.z, p.w)));
            s0[u] = fminf(s0[u], d0);
            s1[u] = fminf(s1[u], d1);
        }
    }

    bitonic32(s0);
    bitonic32(s1);
    const float T0 = s0[15], T1 = s1[15];

    u64 buf0[CAP], buf1[CAP];
    int cnt0 = 0, cnt1 = 0, ovf0 = 0, ovf1 = 0;
    for (int j = 0; j < 2048; j++) {
        float4 p = tile[j];
        float d0 = fmaf(x20, p.x, fmaf(y20, p.y, fmaf(z20, p.z, p.w)));
        float d1 = fmaf(x21, p.x, fmaf(y21, p.y, fmaf(z21, p.z, p.w)));
        if (d0 <= T0) {
            if (cnt0 < CAP) { buf0[cnt0] = pk2(d0, __int_as_float(c0+j)); cnt0++; }
            else ovf0 = 1;
        }
        if (d1 <= T1) {
            if (cnt1 < CAP) { buf1[cnt1] = pk2(d1, __int_as_float(c0+j)); cnt1++; }
            else ovf1 = 1;
        }
    }

    if (ovf0) { exact16(tile, x20, y20, z20, c0, buf0); cnt0 = 16; }
    if (ovf1) { exact16(tile, x21, y21, z21, c0, buf1); cnt1 = 16; }

    {
        const int qg = b*NPTS + i0;
        g_scnt[qg*NPART + quarter] = cnt0;
        u64* dst = g_sbuf + (long long)(qg*NPART + quarter)*CAP;
        for (int t = 0; t < cnt0; t++) dst[t] = buf0[t];
    }
    {
        const int qg = b*NPTS + i1;
        g_scnt[qg*NPART + quarter] = cnt1;
        u64* dst = g_sbuf + (long long)(qg*NPART + quarter)*CAP;
        for (int t = 0; t < cnt1; t++) dst[t] = buf1[t];
    }
}

__global__ __launch_bounds__(256) void knn_merge()
{
    const int q = blockIdx.x*256 + threadIdx.x;
    float bd[16]; int bj[16];
#pragma unroll
    for (int t = 0; t < 16; t++) { bd[t] = 3.4e38f; bj[t] = 0; }
    float cm = 3.4e38f;
#pragma unroll
    for (int h = 0; h < NPART; h++) {
        const int c = g_scnt[q*NPART + h];
        const u64* src = g_sbuf + (long long)(q*NPART + h)*CAP;
        for (int e = 0; e < c; e++) {
            float2 v = up2(src[e]);
            float d = v.x;
            if (d < cm) {
                int am = 0; float mv = bd[0];
#pragma unroll
                for (int u = 1; u < 16; u++) if (bd[u] > mv) { mv = bd[u]; am = u; }
#pragma unroll
                for (int u = 0; u < 16; u++) if (u == am) { bd[u] = d; bj[u] = __float_as_int(v.y); }
                cm = bd[0];
#pragma unroll
                for (int u = 1; u < 16; u++) cm = fmaxf(cm, bd[u]);
            }
        }
    }
#pragma unroll
    for (int t = 0; t < 16; t++) g_idx[q*16 + t] = bj[t];
}

// =====================================================================
// Shared loaders + gemms (act stride 128)
// =====================================================================
template<int KFULL>
__device__ __forceinline__ void ldgA2(float4& r, const float* __restrict__ src,
                                      int koff, int tid)
{
    int o = tid & 63, k4 = tid >> 6;
    r = *(const float4*)(src + o*KFULL + koff + 4*k4);
}
__device__ __forceinline__ void stsA2(float* __restrict__ dst, const float4& r, int tid)
{
    int o = tid & 63, k = (tid >> 6)*4;
    dst[(k  )*64+o] = r.x; dst[(k+1)*64+o] = r.y;
    dst[(k+2)*64+o] = r.z; dst[(k+3)*64+o] = r.w;
}
template<int KFULL>
__device__ __forceinline__ void ldgB2(float4& r, const float* __restrict__ src,
                                      int koff, int tid)
{
    int o = tid & 127, k4 = tid >> 7;
    r = *(const float4*)(src + o*KFULL + koff + 4*k4);
}
__device__ __forceinline__ void stsB2(float* __restrict__ dst, const float4& r, int tid)
{
    int o = tid & 127, k = (tid >> 7)*4;
    dst[(k  )*128+o] = r.x; dst[(k+1)*128+o] = r.y;
    dst[(k+2)*128+o] = r.z; dst[(k+3)*128+o] = r.w;
}

// 8 out (4 pairs) x 4 pos, 16-k chunk. w stride 64, act stride 128.
__device__ __forceinline__ void gemm8d(const float* __restrict__ w,
                                       const float* __restrict__ a,
                                       int og, int pg, u64 acc[4][4])
{
#pragma unroll
    for (int k = 0; k < 16; k++) {
        const float* wr = w + k*64 + og*8;
        ulonglong2 w01 = *(const ulonglong2*)wr;
        ulonglong2 w23 = *(const ulonglong2*)(wr+4);
        u64 wp[4] = {w01.x,w01.y,w23.x,w23.y};
        float4 av = *(const float4*)(a + k*128 + pg*4);
        u64 as[4] = {pk2(av.x,av.x), pk2(av.y,av.y), pk2(av.z,av.z), pk2(av.w,av.w)};
#pragma unroll
        for (int op = 0; op < 4; op++)
#pragma unroll
            for (int p = 0; p < 4; p++) fma2(acc[op][p], wp[op], as[p]);
    }
}

// 16 out (8 pairs) x 4 pos, 8-k chunk. w stride 128, act stride 128.
__device__ __forceinline__ void gemm16d(const float* __restrict__ w,
                                        const float* __restrict__ a,
                                        int og, int pg, u64 acc[8][4])
{
#pragma unroll
    for (int k = 0; k < 8; k++) {
        const float* wr = w + k*128 + og*16;
        ulonglong2 w01 = *(const ulonglong2*)wr;
        ulonglong2 w23 = *(const ulonglong2*)(wr+4);
        ulonglong2 w45 = *(const ulonglong2*)(wr+8);
        ulonglong2 w67 = *(const ulonglong2*)(wr+12);
        u64 wp[8] = {w01.x,w01.y,w23.x,w23.y,w45.x,w45.y,w67.x,w67.y};
        float4 av = *(const float4*)(a + k*128 + pg*4);
        u64 as[4] = {pk2(av.x,av.x), pk2(av.y,av.y), pk2(av.z,av.z), pk2(av.w,av.w)};
#pragma unroll
        for (int op = 0; op < 8; op++)
#pragma unroll
            for (int p = 0; p < 4; p++) fma2(acc[op][p], wp[op], as[p]);
    }
}

// =====================================================================
// Stage 1: 128-pos tiles, 256 thr, 2 CTAs/SM (stage2 template).
// smem: SB1 0 (sc/out1), SB2 8192 (h), SB3 16384 (feat+smallW -> h2),
//       SW0 24576, SW1 25600 -> 26624 floats = 106496 B
// =====================================================================
#define SB1 0
#define SB2 8192
#define SB3 16384
#define SW0 24576
#define SW1 25600
#define S1_FLOATS 26624

__global__ void __launch_bounds__(256,2) stage1_kernel(
    const float* __restrict__ xyz,
    const float* __restrict__ w1sc, const float* __restrict__ b1sc,
    const float* __restrict__ w1a,  const float* __restrict__ b1a,
    const float* __restrict__ w1b,  const float* __restrict__ b1b,
    const float* __restrict__ w1c,  const float* __restrict__ b1c)
{
    extern __shared__ float sm[];
    const int tid = threadIdx.x;
    const int og = tid >> 5, pg = tid & 31;
    const int nl = pg >> 2;                       // thread's n (0..7)
    const int base = blockIdx.x << 7;             // 128 pos
    const int b  = base >> 17;
    const int nb = (base & (NPTS*KNB - 1)) >> 4;

    float* const W[2] = { sm + SW0, sm + SW1 };
    float4 R;

    // ---- prologue: w1b chunk0 ; features -> SB3 ; small weights -> SB3+1280 ----
    ldgA2<64>(R, w1b, 0, tid);
    if (tid < 128) {
        int p = tid;
        int nn = nb + (p >> 4);
        const float* xb = xyz + b*3*NPTS;
        int j = g_idx[(b*NPTS + nn)*KNB + (p & 15)];
        float cx = xb[nn], cy = xb[NPTS+nn], cz = xb[2*NPTS+nn];
        float nx = xb[j],  ny = xb[NPTS+j],  nz = xb[2*NPTS+j];
        float rx = nx-cx, ry = ny-cy, rz = nz-cz;
        float dd = sqrtf(fmaf(rx,rx, fmaf(ry,ry, rz*rz)) + 1e-12f);
        sm[SB3+0*128+p]=cx; sm[SB3+1*128+p]=cy; sm[SB3+2*128+p]=cz;
        sm[SB3+3*128+p]=nx; sm[SB3+4*128+p]=ny; sm[SB3+5*128+p]=nz;
        sm[SB3+6*128+p]=rx; sm[SB3+7*128+p]=ry; sm[SB3+8*128+p]=rz;
        sm[SB3+9*128+p]=dd;
    }
    for (int l = tid; l < 1280; l += 256) {
        if (l < 640) { int o = l/10, k = l - o*10; sm[SB3+1280 + k*64 + o] = w1sc[l]; }
        else { int l2 = l - 640; int o = l2/10, k = l2 - o*10; sm[SB3+1920 + k*64 + o] = w1a[l2]; }
    }
    stsA2(W[0], R, tid);
    __syncthreads();

    // ---- K=10 dual GEMM: h(leaky)->SB2, sc(raw)->SB1 ----
    {
        u64 accS[4][4], accA[4][4];
#pragma unroll
        for (int op=0;op<4;op++)
#pragma unroll
            for (int p=0;p<4;p++) { accS[op][p]=0ull; accA[op][p]=0ull; }
#pragma unroll
        for (int k = 0; k < 10; k++) {
            const float* wsr = sm + SB3 + 1280 + k*64 + og*8;
            const float* war = sm + SB3 + 1920 + k*64 + og*8;
            ulonglong2 ws01 = *(const ulonglong2*)wsr;
            ulonglong2 ws23 = *(const ulonglong2*)(wsr+4);
            ulonglong2 wa01 = *(const ulonglong2*)war;
            ulonglong2 wa23 = *(const ulonglong2*)(war+4);
            u64 wsp[4] = {ws01.x,ws01.y,ws23.x,ws23.y};
            u64 wap[4] = {wa01.x,wa01.y,wa23.x,wa23.y};
            float4 av = *(const float4*)(sm + SB3 + k*128 + pg*4);
            u64 as[4] = {pk2(av.x,av.x), pk2(av.y,av.y), pk2(av.z,av.z), pk2(av.w,av.w)};
#pragma unroll
            for (int op=0;op<4;op++)
#pragma unroll
                for (int p=0;p<4;p++) { fma2(accS[op][p], wsp[op], as[p]); fma2(accA[op][p], wap[op], as[p]); }
        }
#pragma unroll
        for (int op=0;op<4;op++) {
            int o0 = og*8 + 2*op;
            float ba0 = __ldg(b1a + o0), ba1 = __ldg(b1a + o0 + 1);
#pragma unroll
            for (int p=0;p<4;p++) {
                float2 va = up2(accA[op][p]);
                sm[SB2 + (o0  )*128 + pg*4 + p] = leaky(va.x + ba0);
                sm[SB2 + (o0+1)*128 + pg*4 + p] = leaky(va.y + ba1);
                float2 vs = up2(accS[op][p]);
                sm[SB1 + (o0  )*128 + pg*4 + p] = vs.x;
                sm[SB1 + (o0+1)*128 + pg*4 + p] = vs.y;
            }
        }
    }
    __syncthreads();

    u64 acc4[4][4];
#define ZERO4 {_Pragma("unroll") for (int op=0;op<4;op++) _Pragma("unroll") for (int p=0;p<4;p++) acc4[op][p]=0ull;}

    // ---- chunks 0..3: w1b on SB2(h) -> h2 -> SB3 ----
    ZERO4
#pragma unroll
    for (int c = 0; c < 4; c++) {
        if (c < 3) ldgA2<64>(R, w1b, (c+1)*16, tid);
        else       ldgA2<64>(R, w1c, 0, tid);            // chunk 4
        gemm8d(W[c&1], sm + SB2 + c*16*128, og, pg, acc4);
        stsA2(W[1-(c&1)], R, tid);
        __syncthreads();
    }
#pragma unroll
    for (int op=0;op<4;op++) {
        int o0 = og*8 + 2*op;
        float b0 = __ldg(b1b + o0), b1 = __ldg(b1b + o0 + 1);
#pragma unroll
        for (int p=0;p<4;p++) {
            float2 v = up2(acc4[op][p]);
            sm[SB3 + (o0  )*128 + pg*4 + p] = leaky(v.x + b0);
            sm[SB3 + (o0+1)*128 + pg*4 + p] = leaky(v.y + b1);
        }
    }
    __syncthreads();

    // ---- chunks 4..7: w1c on SB3(h2) ; out1 -> SB1 ; x1 ----
    ZERO4
#pragma unroll
    for (int c = 4; c < 7; c++) {
        ldgA2<64>(R, w1c, (c-3)*16, tid);
        gemm8d(W[c&1], sm + SB3 + (c-4)*16*128, og, pg, acc4);
        stsA2(W[1-(c&1)], R, tid);
        __syncthreads();
    }
    gemm8d(W[1], sm + SB3 + 3*16*128, og, pg, acc4);     // chunk 7 (odd)
#pragma unroll
    for (int op=0;op<4;op++) {
        int o0 = og*8 + 2*op;
        float bt0 = __ldg(b1c + o0)     + __ldg(b1sc + o0);
        float bt1 = __ldg(b1c + o0 + 1) + __ldg(b1sc + o0 + 1);
        float v0m = -3.4e38f, v1m = -3.4e38f;
#pragma unroll
        for (int p=0;p<4;p++) {
            float2 v = up2(acc4[op][p]);
            float o0v = v.x + sm[SB1 + (o0  )*128 + pg*4 + p] + bt0;
            float o1v = v.y + sm[SB1 + (o0+1)*128 + pg*4 + p] + bt1;
            sm[SB1 + (o0  )*128 + pg*4 + p] = o0v;
            sm[SB1 + (o0+1)*128 + pg*4 + p] = o1v;
            v0m = fmaxf(v0m, o0v); v1m = fmaxf(v1m, o1v);
        }
        v0m = fmaxf(v0m, __shfl_xor_sync(0xffffffffu, v0m, 1));
        v0m = fmaxf(v0m, __shfl_xor_sync(0xffffffffu, v0m, 2));
        v1m = fmaxf(v1m, __shfl_xor_sync(0xffffffffu, v1m, 1));
        v1m = fmaxf(v1m, __shfl_xor_sync(0xffffffffu, v1m, 2));
        if ((pg & 3) == 0) {
            long long q = (long long)(b*NPTS + nb + nl);
            g_x1[q*64 + o0]     = v0m;
            g_x1[q*64 + o0 + 1] = v1m;
        }
    }
    __syncthreads();
    // out1 tile -> gmem (layout identical to stage2's B1)
    for (int l = tid; l < 2048; l += 256)
        ((float4*)(g_out1 + (long long)blockIdx.x*8192))[l] = ((const float4*)(sm + SB1))[l];
}

// =====================================================================
// Corr kernels (split to tame registers)
// corr_a[n,0:64]   = w2a[:,64:]^T  x1[n]
// corr_sc[n,64:192]= w2sc[:,64:]^T x1[n]
// =====================================================================
#define CX 0        // X1T [64k][128n]  8192

__global__ void __launch_bounds__(256) corr_a_kernel(const float* __restrict__ w2a)
{
    extern __shared__ float sm[];
    float* CWA = sm + 8192;   // [64k][64o] 4096
    const int tid = threadIdx.x;
    const int og = tid >> 5, pg = tid & 31;
    const int nq0 = blockIdx.x*128;

    for (int l = tid; l < 2048; l += 256) {
        int n = l >> 4, k4 = l & 15;
        float4 v = ((const float4*)(g_x1 + (long long)(nq0 + n)*64))[k4];
        sm[CX + (4*k4  )*128 + n] = v.x;
        sm[CX + (4*k4+1)*128 + n] = v.y;
        sm[CX + (4*k4+2)*128 + n] = v.z;
        sm[CX + (4*k4+3)*128 + n] = v.w;
    }
    for (int l = tid; l < 1024; l += 256) {
        int o = l & 63, k4 = l >> 6;
        float4 v = *(const float4*)(w2a + o*128 + 64 + 4*k4);
        CWA[(4*k4  )*64 + o] = v.x;
        CWA[(4*k4+1)*64 + o] = v.y;
        CWA[(4*k4+2)*64 + o] = v.z;
        CWA[(4*k4+3)*64 + o] = v.w;
    }
    __syncthreads();

    u64 acc[4][4];
#pragma unroll
    for (int op=0;op<4;op++)
#pragma unroll
        for (int p=0;p<4;p++) acc[op][p]=0ull;
#pragma unroll
    for (int c = 0; c < 4; c++)
        gemm8d(CWA + c*16*64, sm + CX + c*16*128, og, pg, acc);
#pragma unroll
    for (int op=0;op<4;op++) {
        int o0 = og*8 + 2*op;
#pragma unroll
        for (int p=0;p<4;p++) {
            float2 v = up2(acc[op][p]);
            long long n = nq0 + pg*4 + p;
            g_corr[n*192 + o0]     = v.x;
            g_corr[n*192 + o0 + 1] = v.y;
        }
    }
}

__global__ void __launch_bounds__(256) void_pad();  // (unused fwd decl guard)
__global__ void __launch_bounds__(256) corr_sc_kernel(const float* __restrict__ w2sc)
{
    extern __shared__ float sm[];
    float* CWS = sm + 8192;   // [64k][128o] 8192
    const int tid = threadIdx.x;
    const int og = tid >> 5, pg = tid & 31;
    const int nq0 = blockIdx.x*128;

    for (int l = tid; l < 2048; l += 256) {
        int n = l >> 4, k4 = l & 15;
        float4 v = ((const float4*)(g_x1 + (long long)(nq0 + n)*64))[k4];
        sm[CX + (4*k4  )*128 + n] = v.x;
        sm[CX + (4*k4+1)*128 + n] = v.y;
        sm[CX + (4*k4+2)*128 + n] = v.z;
        sm[CX + (4*k4+3)*128 + n] = v.w;
    }
    for (int l = tid; l < 2048; l += 256) {
        int o = l & 127, k4 = l >> 7;
        float4 v = *(const float4*)(w2sc + o*128 + 64 + 4*k4);
        CWS[(4*k4  )*128 + o] = v.x;
        CWS[(4*k4+1)*128 + o] = v.y;
        CWS[(4*k4+2)*128 + o] = v.z;
        CWS[(4*k4+3)*128 + o] = v.w;
    }
    __syncthreads();

    u64 acc[8][4];
#pragma unroll
    for (int op=0;op<8;op++)
#pragma unroll
        for (int p=0;p<4;p++) acc[op][p]=0ull;
#pragma unroll
    for (int c = 0; c < 8; c++)
        gemm16d(CWS + c*8*128, sm + CX + c*8*128, og, pg, acc);
#pragma unroll
    for (int op=0;op<8;op++) {
        int o0 = og*16 + 2*op;
#pragma unroll
        for (int p=0;p<4;p++) {
            float2 v = up2(acc[op][p]);
            long long n = nq0 + pg*4 + p;
            g_corr[n*192 + 64 + o0]     = v.x;
            g_corr[n*192 + 64 + o0 + 1] = v.y;
        }
    }
}

// =====================================================================
// Stage 2 (unchanged from R14 except straight out1 copy)
// =====================================================================
#define T2B1  0
#define T2B2  8192
#define T2B3  16384
#define T2SW0 24576
#define T2SW1 25600
#define T2SX  26624
#define T2_FLOATS 28160

__global__ void __launch_bounds__(256,2) stage2_kernel(
    const float* __restrict__ w2sc, const float* __restrict__ b2sc,
    const float* __restrict__ w2a,  const float* __restrict__ b2a,
    const float* __restrict__ w2b,  const float* __restrict__ b2b,
    const float* __restrict__ w2c,  const float* __restrict__ b2c,
    float* __restrict__ outp)
{
    extern __shared__ float sm[];
    const int tid = threadIdx.x;
    const int og = tid >> 5, pg = tid & 31;
    const int nl = pg >> 2;
    const int base = blockIdx.x << 7;
    const int b  = base >> 17;
    const int nb = (base & (NPTS*KNB - 1)) >> 4;

    float* const W[2] = { sm + T2SW0, sm + T2SW1 };
    float4 R;

    ldgA2<128>(R, w2a, 0, tid);
    {
        const float4* src = (const float4*)(g_out1 + (long long)blockIdx.x*8192);
        for (int l = tid; l < 2048; l += 256)
            ((float4*)(sm + T2B1))[l] = src[l];
    }
    for (int l = tid; l < 1536; l += 256) {
        int j = l >> 3, q = l & 7;
        sm[T2SX + j*8 + q] = g_corr[(long long)(b*NPTS + nb + q)*192 + j];
    }
    stsA2(W[0], R, tid);
    __syncthreads();

    u64 acc4[4][4];
#define ZERO4B {_Pragma("unroll") for (int op=0;op<4;op++) _Pragma("unroll") for (int p=0;p<4;p++) acc4[op][p]=0ull;}

    ZERO4B
#pragma unroll
    for (int c = 0; c < 4; c++) {
        if (c < 3) { ldgA2<128>(R, w2a, (c+1)*16, tid); }
        else       { ldgB2<64>(R, w2b, 0, tid); }
        gemm8d(W[c&1], sm + T2B1 + c*16*128, og, pg, acc4);
        if (c < 3) stsA2(W[1-(c&1)], R, tid);
        else       stsB2(W[1-(c&1)], R, tid);
        __syncthreads();
    }
#pragma unroll
    for (int op=0;op<4;op++) {
        int o0 = og*8 + 2*op;
        float b0 = __ldg(b2a + o0)     + sm[T2SX + (o0  )*8 + nl];
        float b1 = __ldg(b2a + o0 + 1) + sm[T2SX + (o0+1)*8 + nl];
#pragma unroll
        for (int p=0;p<4;p++) {
            float2 v = up2(acc4[op][p]);
            sm[T2B2 + (o0  )*128 + pg*4 + p] = leaky(v.x + b0);
            sm[T2B2 + (o0+1)*128 + pg*4 + p] = leaky(v.y + b1);
        }
    }
    __syncthreads();

    u64 acc[8][4];
#pragma unroll
    for (int op=0;op<8;op++)
#pragma unroll
        for (int p=0;p<4;p++) acc[op][p]=0ull;
#pragma unroll
    for (int c = 4; c < 12; c++) {
        if (c < 11) ldgB2<64>(R, w2b, (c-3)*8, tid);
        else        ldgB2<128>(R, w2c, 0, tid);
        gemm16d(W[c&1], sm + T2B2 + (c-4)*1024, og, pg, acc);
        stsB2(W[1-(c&1)], R, tid);
        __syncthreads();
    }
#pragma unroll
    for (int op=0;op<8;op++) {
        int o0 = og*16 + 2*op;
        float b0 = __ldg(b2b + o0), b1 = __ldg(b2b + o0+1);
        float* d0 = sm + ((o0 < 64) ? (T2B3 + o0*128) : (T2B2 + (o0-64)*128));
        float* d1 = sm + ((o0+1 < 64) ? (T2B3 + (o0+1)*128) : (T2B2 + (o0+1-64)*128));
#pragma unroll
        for (int p=0;p<4;p++) {
            float2 v = up2(acc[op][p]);
            d0[pg*4 + p] = leaky(v.x + b0);
            d1[pg*4 + p] = leaky(v.y + b1);
        }
    }
    __syncthreads();

#pragma unroll
    for (int op=0;op<8;op++)
#pragma unroll
        for (int p=0;p<4;p++) acc[op][p]=0ull;
#pragma unroll
    for (int c = 12; c < 20; c++) {
        if (c < 19) ldgB2<128>(R, w2c, (c-11)*8, tid);
        else        ldgB2<128>(R, w2c, 64, tid);
        gemm16d(W[c&1], sm + T2B3 + (c-12)*1024, og, pg, acc);
        stsB2(W[1-(c&1)], R, tid);
        __syncthreads();
    }
#pragma unroll
    for (int c = 20; c < 28; c++) {
        if (c < 27) ldgB2<128>(R, w2c, 64 + (c-19)*8, tid);
        else        ldgB2<128>(R, w2sc, 0, tid);
        gemm16d(W[c&1], sm + T2B2 + (c-20)*1024, og, pg, acc);
        stsB2(W[1-(c&1)], R, tid);
        __syncthreads();
    }
#pragma unroll
    for (int c = 28; c < 35; c++) {
        ldgB2<128>(R, w2sc, (c-27)*8, tid);
        gemm16d(W[c&1], sm + T2B1 + (c-28)*1024, og, pg, acc);
        stsB2(W[1-(c&1)], R, tid);
        __syncthreads();
    }
    gemm16d(W[1], sm + T2B1 + 7*1024, og, pg, acc);

#pragma unroll
    for (int op=0;op<8;op++) {
        int o0 = og*16 + 2*op;
        float bt0 = __ldg(b2sc + o0)     + __ldg(b2c + o0)     + sm[T2SX + (64+o0  )*8 + nl];
        float bt1 = __ldg(b2sc + o0 + 1) + __ldg(b2c + o0 + 1) + sm[T2SX + (64+o0+1)*8 + nl];
        float m0 = -3.4e38f, m1 = -3.4e38f;
#pragma unroll
        for (int p=0;p<4;p++) {
            float2 v = up2(acc[op][p]);
            m0 = fmaxf(m0, v.x); m1 = fmaxf(m1, v.y);
        }
        m0 += bt0; m1 += bt1;
        m0 = fmaxf(m0, __shfl_xor_sync(0xffffffffu, m0, 1));
        m0 = fmaxf(m0, __shfl_xor_sync(0xffffffffu, m0, 2));
        m1 = fmaxf(m1, __shfl_xor_sync(0xffffffffu, m1, 1));
        m1 = fmaxf(m1, __shfl_xor_sync(0xffffffffu, m1, 2));
        if ((pg & 3) == 0) {
            outp[((long long)b*128 + o0    )*NPTS + nb + nl] = m0;
            outp[((long long)b*128 + o0 + 1)*NPTS + nb + nl] = m1;
        }
    }
}

__global__ void void_pad() {}

// =====================================================================
extern "C" void kernel_launch(void* const* d_in, const int* in_sizes, int n_in,
                              void* d_out, int out_size)
{
    const float* xyz     = (const float*)d_in[0];
    const float* p1_sc_w = (const float*)d_in[1];
    const float* p1_sc_b = (const float*)d_in[2];
    const float* p1_a_w  = (const float*)d_in[3];
    const float* p1_a_b  = (const float*)d_in[4];
    const float* p1_b_w  = (const float*)d_in[5];
    const float* p1_b_b  = (const float*)d_in[6];
    const float* p1_c_w  = (const float*)d_in[7];
    const float* p1_c_b  = (const float*)d_in[8];
    const float* p2_sc_w = (const float*)d_in[9];
    const float* p2_sc_b = (const float*)d_in[10];
    const float* p2_a_w  = (const float*)d_in[11];
    const float* p2_a_b  = (const float*)d_in[12];
    const float* p2_b_w  = (const float*)d_in[13];
    const float* p2_b_b  = (const float*)d_in[14];
    const float* p2_c_w  = (const float*)d_in[15];
    const float* p2_c_b  = (const float*)d_in[16];
    float* outp = (float*)d_out;

    cudaFuncSetAttribute(stage1_kernel, cudaFuncAttributeMaxDynamicSharedMemorySize,
                         S1_FLOATS*4);
    cudaFuncSetAttribute(corr_a_kernel, cudaFuncAttributeMaxDynamicSharedMemorySize,
                         12288*4);
    cudaFuncSetAttribute(corr_sc_kernel, cudaFuncAttributeMaxDynamicSharedMemorySize,
                         16384*4);
    cudaFuncSetAttribute(stage2_kernel, cudaFuncAttributeMaxDynamicSharedMemorySize,
                         T2_FLOATS*4);

    knn_part<<<512, 128, 32768>>>(xyz);
    knn_merge<<<NQ/256, 256>>>();
    stage1_kernel<<<NPOS/128, 256, S1_FLOATS*4>>>(
        xyz, p1_sc_w, p1_sc_b, p1_a_w, p1_a_b, p1_b_w, p1_b_b, p1_c_w, p1_c_b);
    corr_a_kernel<<<NQ/128, 256, 12288*4>>>(p2_a_w);
    corr_sc_kernel<<<NQ/128, 256, 16384*4>>>(p2_sc_w);
    stage2_kernel<<<NPOS/128, 256, T2_FLOATS*4>>>(
        p2_sc_w, p2_sc_b, p2_a_w, p2_a_b, p2_b_w, p2_b_b, p2_c_w, p2_c_b, outp);
}